// round 6
// baseline (speedup 1.0000x reference)
#include <cuda_runtime.h>
#include <cstdint>

// ===========================================================================
// B=16384, Q=1024, F=2. Heavy GEMMs via mma.sync.m16n8k32.s8 (2x bf16 K-rate,
// exact integer): x ~= s*X, X = 256*hi + lo (s8 planes, QMAX=32512);
// X*Y = 65536*hh + 256*(hi*lo'+lo*hi') + lolo(dropped ~1.6e-5 rel).
// ===========================================================================

#define DEVI __device__ __forceinline__
#define QMAXF 32512.0f
#define QINVF (1.0f / 32512.0f)

DEVI uint32_t smem_u32(const void* p) {
    uint32_t r;
    asm("{ .reg .u64 t; cvta.to.shared.u64 t, %1; cvt.u32.u64 %0, t; }"
        : "=r"(r) : "l"(p));
    return r;
}
DEVI uint32_t swz(uint32_t x) { return x ^ ((x >> 3) & 0x70); }

DEVI void cp16(uint32_t dst, const void* src) {
    asm volatile("cp.async.cg.shared.global [%0], [%1], 16;"
                 :: "r"(dst), "l"(src));
}
#define CP_COMMIT() asm volatile("cp.async.commit_group;" ::: "memory")
#define CP_WAIT(n)  asm volatile("cp.async.wait_group %0;" :: "n"(n) : "memory")

DEVI void ldsm4(uint32_t* r, uint32_t a) {
    asm volatile("ldmatrix.sync.aligned.m8n8.x4.shared.b16 {%0,%1,%2,%3}, [%4];"
                 : "=r"(r[0]), "=r"(r[1]), "=r"(r[2]), "=r"(r[3]) : "r"(a));
}
DEVI void mma_s8(int* d, const uint32_t* a, uint32_t b0, uint32_t b1) {
    asm volatile("mma.sync.aligned.m16n8k32.row.col.s32.s8.s8.s32 "
                 "{%0,%1,%2,%3},{%4,%5,%6,%7},{%8,%9},{%0,%1,%2,%3};"
                 : "+r"(d[0]), "+r"(d[1]), "+r"(d[2]), "+r"(d[3])
                 : "r"(a[0]), "r"(a[1]), "r"(a[2]), "r"(a[3]),
                   "r"(b0), "r"(b1));
}

DEVI void quant2(float v, float inv, int8_t& h, int8_t& l) {
    const int X = __float2int_rn(v * inv);
    const int hh = (X + 128) >> 8;
    h = (int8_t)hh;
    l = (int8_t)(X - (hh << 8));
}

// ---------------------------------------------------------------------------
// Scratch
// ---------------------------------------------------------------------------
__device__ int8_t g_h1h[(size_t)16384 * 4096], g_h1l[(size_t)16384 * 4096];
__device__ int8_t g_pqh[(size_t)16384 * 2048], g_pql[(size_t)16384 * 2048];
__device__ float  g_t2f[(size_t)16384 * 2048];
__device__ int8_t g_t2h[(size_t)16384 * 2048], g_t2l[(size_t)16384 * 2048];
__device__ float  g_ampf[(size_t)16384 * 1024], g_phf[(size_t)16384 * 1024];
__device__ int8_t g_qh[(size_t)16384 * 1024], g_ql[(size_t)16384 * 1024];
__device__ float  g_vf[(size_t)16384 * 1024];
__device__ int8_t g_vqh[(size_t)16384 * 1024], g_vql[(size_t)16384 * 1024];
__device__ int8_t g_w2h[(size_t)2048 * 4096], g_w2l[(size_t)2048 * 4096];
__device__ int8_t g_w3h[(size_t)1024 * 2048], g_w3l[(size_t)1024 * 2048];
__device__ int8_t g_pw2h[(size_t)1024 * 2048], g_pw2l[(size_t)1024 * 2048];
__device__ int8_t g_wvh[(size_t)1024 * 1024], g_wvl[(size_t)1024 * 1024];
__device__ int8_t g_woh[(size_t)1024 * 1024], g_wol[(size_t)1024 * 1024];
__device__ float g_sH1[16384], g_sP[16384], g_sT2[16384], g_sQS[16384], g_sV[16384];
__device__ float g_sW2[2048], g_sW3[1024], g_sPW2[1024], g_sWV[1024], g_sWO[1024];

// ---------------------------------------------------------------------------
// Reductions
// ---------------------------------------------------------------------------
DEVI float2 block_reduce2(float2 v, float2* sbuf) {
    const int lane = threadIdx.x & 31, wid = threadIdx.x >> 5;
#pragma unroll
    for (int o = 16; o > 0; o >>= 1) {
        v.x += __shfl_xor_sync(0xffffffffu, v.x, o);
        v.y += __shfl_xor_sync(0xffffffffu, v.y, o);
    }
    if (lane == 0) sbuf[wid] = v;
    __syncthreads();
    if (wid == 0) {
        float2 t = (lane < 8) ? sbuf[lane] : make_float2(0.f, 0.f);
#pragma unroll
        for (int o = 4; o > 0; o >>= 1) {
            t.x += __shfl_xor_sync(0xffffffffu, t.x, o);
            t.y += __shfl_xor_sync(0xffffffffu, t.y, o);
        }
        if (lane == 0) sbuf[0] = t;
    }
    __syncthreads();
    float2 r = sbuf[0];
    __syncthreads();
    return r;
}
DEVI float block_max(float v, float* sm) {
    const int lane = threadIdx.x & 31, wid = threadIdx.x >> 5;
#pragma unroll
    for (int o = 16; o > 0; o >>= 1)
        v = fmaxf(v, __shfl_xor_sync(0xffffffffu, v, o));
    if (lane == 0) sm[wid] = v;
    __syncthreads();
    if (wid == 0) {
        float t = (lane < 8) ? sm[lane] : 0.f;
#pragma unroll
        for (int o = 4; o > 0; o >>= 1)
            t = fmaxf(t, __shfl_xor_sync(0xffffffffu, t, o));
        if (lane == 0) sm[0] = t;
    }
    __syncthreads();
    float r = sm[0];
    __syncthreads();
    return r;
}

// ---------------------------------------------------------------------------
// Weight quantization: per row n of W (N,K): s8 hi/lo planes + scale
// ---------------------------------------------------------------------------
__global__ __launch_bounds__(256)
void wquant(const float* __restrict__ W, int8_t* __restrict__ hi,
            int8_t* __restrict__ lo, float* __restrict__ sc, int K)
{
    __shared__ float sm[8];
    const int n = blockIdx.x;
    const float* row = W + (size_t)n * K;
    float mx = 0.f;
    for (int i = threadIdx.x; i < K; i += 256) mx = fmaxf(mx, fabsf(row[i]));
    mx = block_max(mx, sm);
    const float inv = (mx > 0.f) ? QMAXF / mx : 0.f;
    if (threadIdx.x == 0) sc[n] = (mx > 0.f) ? mx * QINVF : 1.f;
    for (int i = threadIdx.x; i < K; i += 256) {
        int8_t h, l;
        quant2(row[i], inv, h, l);
        hi[(size_t)n * K + i] = h;
        lo[(size_t)n * K + i] = l;
    }
}

// ---------------------------------------------------------------------------
// Layer-1 (F=2 matvec + LN + act) fused with quantization
// ---------------------------------------------------------------------------
__global__ __launch_bounds__(256)
void layer1_q(const float* __restrict__ x,
              const float* __restrict__ aW1, const float* __restrict__ ab1,
              const float* __restrict__ ag1, const float* __restrict__ abe1,
              const float* __restrict__ pW1, const float* __restrict__ pb1,
              const float* __restrict__ pg1, const float* __restrict__ pbe1,
              int8_t* __restrict__ h1h, int8_t* __restrict__ h1l, float* __restrict__ sH1,
              int8_t* __restrict__ pqh, int8_t* __restrict__ pql, float* __restrict__ sP)
{
    __shared__ float2 sbuf[8];
    __shared__ float sm[8];
    const int b = blockIdx.x, tid = threadIdx.x;
    const float x0 = x[2 * b], x1 = x[2 * b + 1];

    // amp branch: 4096
    {
        float g[4][4];
        float2 ss = make_float2(0.f, 0.f);
#pragma unroll
        for (int t = 0; t < 4; t++) {
            const int i0 = tid * 4 + t * 1024;
            const float4 wa = *(const float4*)&aW1[2 * i0];
            const float4 wb = *(const float4*)&aW1[2 * i0 + 4];
            const float4 bb = *(const float4*)&ab1[i0];
            g[t][0] = fmaf(wa.y, x1, fmaf(wa.x, x0, bb.x));
            g[t][1] = fmaf(wa.w, x1, fmaf(wa.z, x0, bb.y));
            g[t][2] = fmaf(wb.y, x1, fmaf(wb.x, x0, bb.z));
            g[t][3] = fmaf(wb.w, x1, fmaf(wb.z, x0, bb.w));
#pragma unroll
            for (int j = 0; j < 4; j++) { ss.x += g[t][j]; ss.y += g[t][j] * g[t][j]; }
        }
        const float2 r = block_reduce2(ss, sbuf);
        const float m = r.x * (1.f / 4096.f);
        const float rstd = rsqrtf(r.y * (1.f / 4096.f) - m * m + 1e-5f);
        float mx = 0.f;
#pragma unroll
        for (int t = 0; t < 4; t++) {
            const int i0 = tid * 4 + t * 1024;
            const float4 gg = *(const float4*)&ag1[i0];
            const float4 be = *(const float4*)&abe1[i0];
            const float gv[4] = {gg.x, gg.y, gg.z, gg.w};
            const float bv[4] = {be.x, be.y, be.z, be.w};
#pragma unroll
            for (int j = 0; j < 4; j++) {
                const float hh = (g[t][j] - m) * rstd * gv[j] + bv[j];
                const float gl = 0.5f * hh * (1.f + erff(hh * 0.70710678118654752f));
                g[t][j] = gl;
                mx = fmaxf(mx, fabsf(gl));
            }
        }
        mx = block_max(mx, sm);
        const float inv = (mx > 0.f) ? QMAXF / mx : 0.f;
        if (tid == 0) sH1[b] = (mx > 0.f) ? mx * QINVF : 1.f;
#pragma unroll
        for (int t = 0; t < 4; t++) {
            const int i0 = tid * 4 + t * 1024;
            char4 ch, cl;
            quant2(g[t][0], inv, (int8_t&)ch.x, (int8_t&)cl.x);
            quant2(g[t][1], inv, (int8_t&)ch.y, (int8_t&)cl.y);
            quant2(g[t][2], inv, (int8_t&)ch.z, (int8_t&)cl.z);
            quant2(g[t][3], inv, (int8_t&)ch.w, (int8_t&)cl.w);
            *(char4*)&h1h[(size_t)b * 4096 + i0] = ch;
            *(char4*)&h1l[(size_t)b * 4096 + i0] = cl;
        }
    }

    // phase branch: 2048
    {
        float g[2][4];
        float2 ss = make_float2(0.f, 0.f);
#pragma unroll
        for (int t = 0; t < 2; t++) {
            const int i0 = tid * 4 + t * 1024;
            const float4 wa = *(const float4*)&pW1[2 * i0];
            const float4 wb = *(const float4*)&pW1[2 * i0 + 4];
            const float4 bb = *(const float4*)&pb1[i0];
            g[t][0] = fmaf(wa.y, x1, fmaf(wa.x, x0, bb.x));
            g[t][1] = fmaf(wa.w, x1, fmaf(wa.z, x0, bb.y));
            g[t][2] = fmaf(wb.y, x1, fmaf(wb.x, x0, bb.z));
            g[t][3] = fmaf(wb.w, x1, fmaf(wb.z, x0, bb.w));
#pragma unroll
            for (int j = 0; j < 4; j++) { ss.x += g[t][j]; ss.y += g[t][j] * g[t][j]; }
        }
        const float2 r = block_reduce2(ss, sbuf);
        const float m = r.x * (1.f / 2048.f);
        const float rstd = rsqrtf(r.y * (1.f / 2048.f) - m * m + 1e-5f);
        float mx = 0.f;
#pragma unroll
        for (int t = 0; t < 2; t++) {
            const int i0 = tid * 4 + t * 1024;
            const float4 gg = *(const float4*)&pg1[i0];
            const float4 be = *(const float4*)&pbe1[i0];
            const float gv[4] = {gg.x, gg.y, gg.z, gg.w};
            const float bv[4] = {be.x, be.y, be.z, be.w};
#pragma unroll
            for (int j = 0; j < 4; j++) {
                const float hh = (g[t][j] - m) * rstd * gv[j] + bv[j];
                const float s = hh / (1.f + expf(-hh));
                g[t][j] = s;
                mx = fmaxf(mx, fabsf(s));
            }
        }
        mx = block_max(mx, sm);
        const float inv = (mx > 0.f) ? QMAXF / mx : 0.f;
        if (tid == 0) sP[b] = (mx > 0.f) ? mx * QINVF : 1.f;
#pragma unroll
        for (int t = 0; t < 2; t++) {
            const int i0 = tid * 4 + t * 1024;
            char4 ch, cl;
            quant2(g[t][0], inv, (int8_t&)ch.x, (int8_t&)cl.x);
            quant2(g[t][1], inv, (int8_t&)ch.y, (int8_t&)cl.y);
            quant2(g[t][2], inv, (int8_t&)ch.z, (int8_t&)cl.z);
            quant2(g[t][3], inv, (int8_t&)ch.w, (int8_t&)cl.w);
            *(char4*)&pqh[(size_t)b * 2048 + i0] = ch;
            *(char4*)&pql[(size_t)b * 2048 + i0] = cl;
        }
    }
}

// ---------------------------------------------------------------------------
// LN + tanh (row 2048), fixed-scale quantization (|tanh|<=1)
// ---------------------------------------------------------------------------
__global__ __launch_bounds__(256)
void ln_tanh_q(const float* __restrict__ in,
               const float* __restrict__ g, const float* __restrict__ be,
               int8_t* __restrict__ oh, int8_t* __restrict__ ol, float* __restrict__ sc)
{
    __shared__ float2 sbuf[8];
    const int b = blockIdx.x, tid = threadIdx.x;
    const float* row = in + (size_t)b * 2048;
    float va[2][4];
    float2 ss = make_float2(0.f, 0.f);
#pragma unroll
    for (int t = 0; t < 2; t++) {
        const int i0 = tid * 4 + t * 1024;
        const float4 v = *(const float4*)&row[i0];
        va[t][0] = v.x; va[t][1] = v.y; va[t][2] = v.z; va[t][3] = v.w;
#pragma unroll
        for (int j = 0; j < 4; j++) { ss.x += va[t][j]; ss.y += va[t][j] * va[t][j]; }
    }
    const float2 r = block_reduce2(ss, sbuf);
    const float m = r.x * (1.f / 2048.f);
    const float rstd = rsqrtf(r.y * (1.f / 2048.f) - m * m + 1e-5f);
    if (tid == 0) sc[b] = QINVF;
#pragma unroll
    for (int t = 0; t < 2; t++) {
        const int i0 = tid * 4 + t * 1024;
        const float4 gg = *(const float4*)&g[i0];
        const float4 bb = *(const float4*)&be[i0];
        const float gv[4] = {gg.x, gg.y, gg.z, gg.w};
        const float bv[4] = {bb.x, bb.y, bb.z, bb.w};
        char4 ch, cl;
        int8_t h, l;
#pragma unroll
        for (int j = 0; j < 4; j++) {
            const float v = tanhf((va[t][j] - m) * rstd * gv[j] + bv[j]);
            quant2(v, QMAXF, h, l);
            if (j == 0) { ch.x = h; cl.x = l; }
            if (j == 1) { ch.y = h; cl.y = l; }
            if (j == 2) { ch.z = h; cl.z = l; }
            if (j == 3) { ch.w = h; cl.w = l; }
        }
        *(char4*)&oh[(size_t)b * 2048 + i0] = ch;
        *(char4*)&ol[(size_t)b * 2048 + i0] = cl;
    }
}

// ---------------------------------------------------------------------------
// qs mixing (row 1024), fixed-scale quantization (|qs|<1)
// ---------------------------------------------------------------------------
__global__ __launch_bounds__(256)
void qs_q(const float* __restrict__ amp, const float* __restrict__ phv,
          const float* __restrict__ rf, const float* __restrict__ rp,
          int8_t* __restrict__ qh, int8_t* __restrict__ ql, float* __restrict__ sc)
{
    const int b = blockIdx.x, tid = threadIdx.x;
    const int q0 = tid * 4;
    const float4 a = *(const float4*)&amp[(size_t)b * 1024 + q0];
    const float4 p = *(const float4*)&phv[(size_t)b * 1024 + q0];
    const float av[4] = {a.x, a.y, a.z, a.w};
    const float pv[4] = {p.x, p.y, p.z, p.w};
    if (tid == 0) sc[b] = QINVF;
    char4 ch, cl;
    int8_t h, l;
#pragma unroll
    for (int j = 0; j < 4; j++) {
        const int q = q0 + j;
        const float* f  = rf + 4 * 1024 * 3 + 3 * q;
        const float* pp = rp + 4 * 1024 * 3 + 3 * q;
        const float rx = sinf(fmaf(av[j], f[0], pp[0]));
        const float ry = cosf(fmaf(pv[j], f[1], pp[1]));
        const float rz = tanhf(pp[2]);
        const float v = (rx + ry + rz) * (1.f / 3.f);
        quant2(v, QMAXF, h, l);
        if (j == 0) { ch.x = h; cl.x = l; }
        if (j == 1) { ch.y = h; cl.y = l; }
        if (j == 2) { ch.z = h; cl.z = l; }
        if (j == 3) { ch.w = h; cl.w = l; }
    }
    *(char4*)&qh[(size_t)b * 1024 + q0] = ch;
    *(char4*)&ql[(size_t)b * 1024 + q0] = cl;
}

// ---------------------------------------------------------------------------
// Row quantization for v (row 1024, real max)
// ---------------------------------------------------------------------------
__global__ __launch_bounds__(256)
void rowquant(const float* __restrict__ in, int8_t* __restrict__ oh,
              int8_t* __restrict__ ol, float* __restrict__ sc)
{
    __shared__ float sm[8];
    const int b = blockIdx.x, tid = threadIdx.x;
    const int i0 = tid * 4;
    const float4 v = *(const float4*)&in[(size_t)b * 1024 + i0];
    const float vv[4] = {v.x, v.y, v.z, v.w};
    float mx = fmaxf(fmaxf(fabsf(v.x), fabsf(v.y)), fmaxf(fabsf(v.z), fabsf(v.w)));
    mx = block_max(mx, sm);
    const float inv = (mx > 0.f) ? QMAXF / mx : 0.f;
    if (tid == 0) sc[b] = (mx > 0.f) ? mx * QINVF : 1.f;
    char4 ch, cl;
    int8_t h, l;
#pragma unroll
    for (int j = 0; j < 4; j++) {
        quant2(vv[j], inv, h, l);
        if (j == 0) { ch.x = h; cl.x = l; }
        if (j == 1) { ch.y = h; cl.y = l; }
        if (j == 2) { ch.z = h; cl.z = l; }
        if (j == 3) { ch.w = h; cl.w = l; }
    }
    *(char4*)&oh[(size_t)b * 1024 + i0] = ch;
    *(char4*)&ol[(size_t)b * 1024 + i0] = cl;
}

// ---------------------------------------------------------------------------
// int8 GEMM: C[m,n] = sA[m]*sB[n]*(65536*hh + 256*cross) + bias[n]
// 128x128 tile, K-chunk 128 (rows of 128 B, SW128), 3-stage cp.async,
// 8 warps x (64x32) of mma.sync m16n8k32 s8. EPI: 0 = fp32, 1 = tanh
// ---------------------------------------------------------------------------
template<int EPI>
__global__ __launch_bounds__(256, 1)
void gemm_s8(const int8_t* __restrict__ Ahp, const int8_t* __restrict__ Alp,
             const int8_t* __restrict__ Bhp, const int8_t* __restrict__ Blp,
             const float* __restrict__ sA, const float* __restrict__ sB,
             const float* __restrict__ bias, float* __restrict__ Cf,
             int N, int K)
{
    extern __shared__ char smem[];
    const uint32_t sb0 = smem_u32(smem);
    const uint32_t TILES = (sb0 + 1023u) & ~1023u;

    const int tid = threadIdx.x, wid = tid >> 5, lane = tid & 31;
    const int bm = blockIdx.y * 128, bn = blockIdx.x * 128;
    const int warp_m = wid & 1, warp_n = wid >> 1;
    const int nC = K >> 7;

    auto load_chunk = [&](int ci, int s) {
        const int k0 = ci << 7;
        const uint32_t stg = TILES + s * 65536;
#pragma unroll
        for (int t = 0; t < 4; t++) {
            const int g = tid + t * 256;
            const int row = g >> 3;
            const int c16 = (g & 7) * 16;
            const uint32_t so = swz((uint32_t)(row * 128 + c16));
            const size_t ia = (size_t)(bm + row) * K + k0 + c16;
            const size_t ib = (size_t)(bn + row) * K + k0 + c16;
            cp16(stg + so,         Ahp + ia);
            cp16(stg + 16384 + so, Alp + ia);
            cp16(stg + 32768 + so, Bhp + ib);
            cp16(stg + 49152 + so, Blp + ib);
        }
        CP_COMMIT();
    };

    // ldmatrix per-lane base offsets (byte units; rows are 128 B)
    const uint32_t rA = (uint32_t)(warp_m * 64 + (lane & 7) + ((lane >> 3) & 1) * 8) * 128
                      + (uint32_t)(lane >> 4) * 16;
    const uint32_t rB = (uint32_t)(warp_n * 32 + (lane & 15)) * 128
                      + (uint32_t)(lane >> 4) * 16;

    int acc_h[4][4][4], acc_x[4][4][4];
#pragma unroll
    for (int i = 0; i < 4; i++)
#pragma unroll
        for (int j = 0; j < 4; j++)
#pragma unroll
            for (int e = 0; e < 4; e++) { acc_h[i][j][e] = 0; acc_x[i][j][e] = 0; }

    load_chunk(0, 0);
    load_chunk(1, 1);

    for (int i = 0; i < nC; i++) {
        const int s = i - (i / 3) * 3;
        if (i + 1 < nC) { CP_WAIT(1); } else { CP_WAIT(0); }
        __syncthreads();
        if (i + 2 < nC) load_chunk(i + 2, (i + 2) - ((i + 2) / 3) * 3);

        const uint32_t stg = TILES + s * 65536;
        const uint32_t Ahb = stg, Alb = stg + 16384;
        const uint32_t Bhb = stg + 32768, Blb = stg + 49152;

#pragma unroll
        for (int ks = 0; ks < 4; ks++) {
            const uint32_t kb = ks * 32;
            const uint32_t oB0 = swz(rB + kb);
            const uint32_t oB1 = swz(rB + 16 * 128 + kb);
            uint32_t bh0[4], bh1[4], bl0[4], bl1[4];
            ldsm4(bh0, Bhb + oB0);
            ldsm4(bh1, Bhb + oB1);
            ldsm4(bl0, Blb + oB0);
            ldsm4(bl1, Blb + oB1);
#pragma unroll
            for (int mi = 0; mi < 4; mi++) {
                const uint32_t oA = swz(rA + (uint32_t)(mi * 16 * 128) + kb);
                uint32_t ah[4], al[4];
                ldsm4(ah, Ahb + oA);
                ldsm4(al, Alb + oA);
#pragma unroll
                for (int ni = 0; ni < 4; ni++) {
                    const uint32_t* bhp = (ni < 2) ? bh0 : bh1;
                    const uint32_t* blp = (ni < 2) ? bl0 : bl1;
                    const int sel = ni & 1;
                    const uint32_t b_h0 = bhp[sel], b_h1 = bhp[sel + 2];
                    const uint32_t b_l0 = blp[sel], b_l1 = blp[sel + 2];
                    mma_s8(acc_h[mi][ni], ah, b_h0, b_h1);
                    mma_s8(acc_x[mi][ni], ah, b_l0, b_l1);
                    mma_s8(acc_x[mi][ni], al, b_h0, b_h1);
                }
            }
        }
    }

    // ---- Epilogue ----
    const int r0l   = lane >> 2;
    const int cpair = (lane & 3) * 2;
    const int mbase = bm + warp_m * 64;
    const int nbase = bn + warp_n * 32;

#pragma unroll
    for (int mi = 0; mi < 4; mi++) {
        const int row0 = mbase + mi * 16 + r0l;
        const int row1 = row0 + 8;
        const float sa0 = sA[row0], sa1 = sA[row1];
#pragma unroll
        for (int ni = 0; ni < 4; ni++) {
            const int col = nbase + ni * 8 + cpair;
            const float2 bv  = *(const float2*)&bias[col];
            const float2 sbv = *(const float2*)&sB[col];
            float v0 = fmaf(65536.f, (float)acc_h[mi][ni][0], 256.f * (float)acc_x[mi][ni][0]);
            float v1 = fmaf(65536.f, (float)acc_h[mi][ni][1], 256.f * (float)acc_x[mi][ni][1]);
            float v2 = fmaf(65536.f, (float)acc_h[mi][ni][2], 256.f * (float)acc_x[mi][ni][2]);
            float v3 = fmaf(65536.f, (float)acc_h[mi][ni][3], 256.f * (float)acc_x[mi][ni][3]);
            v0 = fmaf(sa0 * sbv.x, v0, bv.x);
            v1 = fmaf(sa0 * sbv.y, v1, bv.y);
            v2 = fmaf(sa1 * sbv.x, v2, bv.x);
            v3 = fmaf(sa1 * sbv.y, v3, bv.y);
            if (EPI == 1) { v0 = tanhf(v0); v1 = tanhf(v1); v2 = tanhf(v2); v3 = tanhf(v3); }
            *(float2*)&Cf[(size_t)row0 * N + col] = make_float2(v0, v1);
            *(float2*)&Cf[(size_t)row1 * N + col] = make_float2(v2, v3);
        }
    }
}

// ---------------------------------------------------------------------------
extern "C" void kernel_launch(void* const* d_in, const int* in_sizes, int n_in,
                              void* d_out, int out_size)
{
    const float* x    = (const float*)d_in[0];
    const float* aW1  = (const float*)d_in[1];
    const float* ab1  = (const float*)d_in[2];
    const float* ag1  = (const float*)d_in[3];
    const float* abe1 = (const float*)d_in[4];
    const float* aW2  = (const float*)d_in[5];
    const float* ab2  = (const float*)d_in[6];
    const float* ag2  = (const float*)d_in[7];
    const float* abe2 = (const float*)d_in[8];
    const float* aW3  = (const float*)d_in[9];
    const float* ab3  = (const float*)d_in[10];
    const float* pW1  = (const float*)d_in[11];
    const float* pb1  = (const float*)d_in[12];
    const float* pg1  = (const float*)d_in[13];
    const float* pbe1 = (const float*)d_in[14];
    const float* pW2  = (const float*)d_in[15];
    const float* pb2  = (const float*)d_in[16];
    const float* rf   = (const float*)d_in[17];
    const float* rp   = (const float*)d_in[18];
    const float* winV = (const float*)d_in[19] + (size_t)2048 * 1024;
    const float* binV = (const float*)d_in[20] + 2048;
    const float* wout = (const float*)d_in[21];
    const float* bout = (const float*)d_in[22];
    float* out = (float*)d_out;

    int8_t *h1h, *h1l, *pqh, *pql, *t2h, *t2l, *qh, *ql, *vqh, *vql;
    int8_t *w2h, *w2l, *w3h, *w3l, *pw2h, *pw2l, *wvh, *wvl, *woh, *wol;
    float *t2f, *ampf, *phf, *vf;
    float *sH1, *sP, *sT2, *sQS, *sV, *sW2, *sW3, *sPW2, *sWV, *sWO;
    cudaGetSymbolAddress((void**)&h1h, g_h1h); cudaGetSymbolAddress((void**)&h1l, g_h1l);
    cudaGetSymbolAddress((void**)&pqh, g_pqh); cudaGetSymbolAddress((void**)&pql, g_pql);
    cudaGetSymbolAddress((void**)&t2f, g_t2f);
    cudaGetSymbolAddress((void**)&t2h, g_t2h); cudaGetSymbolAddress((void**)&t2l, g_t2l);
    cudaGetSymbolAddress((void**)&ampf, g_ampf); cudaGetSymbolAddress((void**)&phf, g_phf);
    cudaGetSymbolAddress((void**)&qh, g_qh); cudaGetSymbolAddress((void**)&ql, g_ql);
    cudaGetSymbolAddress((void**)&vf, g_vf);
    cudaGetSymbolAddress((void**)&vqh, g_vqh); cudaGetSymbolAddress((void**)&vql, g_vql);
    cudaGetSymbolAddress((void**)&w2h, g_w2h); cudaGetSymbolAddress((void**)&w2l, g_w2l);
    cudaGetSymbolAddress((void**)&w3h, g_w3h); cudaGetSymbolAddress((void**)&w3l, g_w3l);
    cudaGetSymbolAddress((void**)&pw2h, g_pw2h); cudaGetSymbolAddress((void**)&pw2l, g_pw2l);
    cudaGetSymbolAddress((void**)&wvh, g_wvh); cudaGetSymbolAddress((void**)&wvl, g_wvl);
    cudaGetSymbolAddress((void**)&woh, g_woh); cudaGetSymbolAddress((void**)&wol, g_wol);
    cudaGetSymbolAddress((void**)&sH1, g_sH1); cudaGetSymbolAddress((void**)&sP, g_sP);
    cudaGetSymbolAddress((void**)&sT2, g_sT2); cudaGetSymbolAddress((void**)&sQS, g_sQS);
    cudaGetSymbolAddress((void**)&sV, g_sV);
    cudaGetSymbolAddress((void**)&sW2, g_sW2); cudaGetSymbolAddress((void**)&sW3, g_sW3);
    cudaGetSymbolAddress((void**)&sPW2, g_sPW2); cudaGetSymbolAddress((void**)&sWV, g_sWV);
    cudaGetSymbolAddress((void**)&sWO, g_sWO);

    const int SMEMB = 1024 + 3 * 65536;
    cudaFuncSetAttribute(gemm_s8<0>, cudaFuncAttributeMaxDynamicSharedMemorySize, SMEMB);
    cudaFuncSetAttribute(gemm_s8<1>, cudaFuncAttributeMaxDynamicSharedMemorySize, SMEMB);

    const int M = 16384;

    // (ordered so the ncu -s 5 window lands on layer1/gemm1)
    wquant<<<2048, 256>>>(aW2, w2h, w2l, sW2, 4096);
    wquant<<<1024, 256>>>(aW3, w3h, w3l, sW3, 2048);
    wquant<<<1024, 256>>>(pW2, pw2h, pw2l, sPW2, 2048);
    layer1_q<<<M, 256>>>(x, aW1, ab1, ag1, abe1, pW1, pb1, pg1, pbe1,
                         h1h, h1l, sH1, pqh, pql, sP);

    // GEMM1: t2 = h1 @ W2^T + b2  (16384x2048, K=4096)
    gemm_s8<0><<<dim3(16, 128), 256, SMEMB>>>(h1h, h1l, w2h, w2l, sH1, sW2, ab2,
                                              t2f, 2048, 4096);
    wquant<<<1024, 256>>>(winV, wvh, wvl, sWV, 1024);
    wquant<<<1024, 256>>>(wout, woh, wol, sWO, 1024);
    ln_tanh_q<<<M, 256>>>(t2f, ag2, abe2, t2h, t2l, sT2);

    // amp = t2 @ W3^T + b3
    gemm_s8<0><<<dim3(8, 128), 256, SMEMB>>>(t2h, t2l, w3h, w3l, sT2, sW3, ab3,
                                             ampf, 1024, 2048);
    // phase = tanh(p @ pW2^T + pb2)
    gemm_s8<1><<<dim3(8, 128), 256, SMEMB>>>(pqh, pql, pw2h, pw2l, sP, sPW2, pb2,
                                             phf, 1024, 2048);
    // qs mixing -> int8 planes (fixed scale)
    qs_q<<<M, 256>>>(ampf, phf, rf, rp, qh, ql, sQS);

    // v = qs @ Wv^T + bv
    gemm_s8<0><<<dim3(8, 128), 256, SMEMB>>>(qh, ql, wvh, wvl, sQS, sWV, binV,
                                             vf, 1024, 1024);
    rowquant<<<M, 256>>>(vf, vqh, vql, sV);

    // out = v @ Wout^T + bout
    gemm_s8<0><<<dim3(8, 128), 256, SMEMB>>>(vqh, vql, woh, wol, sV, sWO, bout,
                                             out, 1024, 1024);
}

// round 7
// speedup vs baseline: 2.8815x; 2.8815x over previous
#include <cuda_runtime.h>
#include <cuda_bf16.h>
#include <cstdint>

// ===========================================================================
// B=16384, Q=1024, F=2. Heavy GEMMs: mma.sync m16n8k16 bf16 with hi/lo split
// (A*B ~= Ah*Bh + Ah*Bl + Al*Bh). CTA tile 128(M)x256(N), warp tile 64x64,
// K-chunk 64, 2-stage cp.async ring. int8/IMMA path abandoned (3x slower).
// ===========================================================================

#define DEVI __device__ __forceinline__

DEVI uint32_t smem_u32(const void* p) {
    uint32_t r;
    asm("{ .reg .u64 t; cvta.to.shared.u64 t, %1; cvt.u32.u64 %0, t; }"
        : "=r"(r) : "l"(p));
    return r;
}
DEVI uint32_t swz(uint32_t x) { return x ^ ((x >> 3) & 0x70); }

DEVI void cp16(uint32_t dst, const void* src) {
    asm volatile("cp.async.cg.shared.global [%0], [%1], 16;"
                 :: "r"(dst), "l"(src));
}
#define CP_COMMIT() asm volatile("cp.async.commit_group;" ::: "memory")
#define CP_WAIT(n)  asm volatile("cp.async.wait_group %0;" :: "n"(n) : "memory")

DEVI void ldsm4(uint32_t* r, uint32_t a) {
    asm volatile("ldmatrix.sync.aligned.m8n8.x4.shared.b16 {%0,%1,%2,%3}, [%4];"
                 : "=r"(r[0]), "=r"(r[1]), "=r"(r[2]), "=r"(r[3]) : "r"(a));
}
DEVI void mma_bf16(float* d, const uint32_t* a, const uint32_t* b) {
    asm volatile("mma.sync.aligned.m16n8k16.row.col.f32.bf16.bf16.f32 "
                 "{%0,%1,%2,%3},{%4,%5,%6,%7},{%8,%9},{%0,%1,%2,%3};"
                 : "+f"(d[0]), "+f"(d[1]), "+f"(d[2]), "+f"(d[3])
                 : "r"(a[0]), "r"(a[1]), "r"(a[2]), "r"(a[3]),
                   "r"(b[0]), "r"(b[1]));
}

DEVI void split_bf(float v, __nv_bfloat16& h, __nv_bfloat16& l) {
    h = __float2bfloat16(v);
    l = __float2bfloat16(v - __bfloat162float(h));
}
DEVI uint32_t pack2(__nv_bfloat16 a, __nv_bfloat16 b) {
    return (uint32_t)__bfloat16_as_ushort(a) | ((uint32_t)__bfloat16_as_ushort(b) << 16);
}

// ---------------------------------------------------------------------------
// Scratch
// ---------------------------------------------------------------------------
__device__ __nv_bfloat16 g_h1h[(size_t)16384 * 4096], g_h1l[(size_t)16384 * 4096];
__device__ __nv_bfloat16 g_ph_h[(size_t)16384 * 2048], g_ph_l[(size_t)16384 * 2048];
__device__ float         g_t2f[(size_t)16384 * 2048];
__device__ __nv_bfloat16 g_t2h[(size_t)16384 * 2048], g_t2l[(size_t)16384 * 2048];
__device__ float         g_ampf[(size_t)16384 * 1024], g_phf[(size_t)16384 * 1024];
__device__ __nv_bfloat16 g_qsh[(size_t)16384 * 1024], g_qsl[(size_t)16384 * 1024];
__device__ __nv_bfloat16 g_vh[(size_t)16384 * 1024],  g_vl[(size_t)16384 * 1024];
__device__ __nv_bfloat16 g_w2h[(size_t)2048 * 4096], g_w2l[(size_t)2048 * 4096];
__device__ __nv_bfloat16 g_w3h[(size_t)1024 * 2048], g_w3l[(size_t)1024 * 2048];
__device__ __nv_bfloat16 g_pw2h[(size_t)1024 * 2048], g_pw2l[(size_t)1024 * 2048];
__device__ __nv_bfloat16 g_wvh[(size_t)1024 * 1024], g_wvl[(size_t)1024 * 1024];
__device__ __nv_bfloat16 g_woh[(size_t)1024 * 1024], g_wol[(size_t)1024 * 1024];

// ---------------------------------------------------------------------------
// GEMM: C[m,n] = sum_k A[m,k]*W[n,k] + bias[n]
// EPI: 0 = fp32 store; 2 = bf16 hi/lo split store; 3 = merged two-GEMM launch
//      (blockIdx.z==0 -> set 0 plain fp32, z==1 -> set 1 with tanh)
// ---------------------------------------------------------------------------
template<int EPI>
__global__ __launch_bounds__(256, 1)
void gemm_bf3(const __nv_bfloat16* __restrict__ Ahi, const __nv_bfloat16* __restrict__ Alo,
              const __nv_bfloat16* __restrict__ Bhi, const __nv_bfloat16* __restrict__ Blo,
              const float* __restrict__ bias, float* __restrict__ Cf,
              __nv_bfloat16* __restrict__ Chi, __nv_bfloat16* __restrict__ Clo,
              const __nv_bfloat16* Ahi2, const __nv_bfloat16* Alo2,
              const __nv_bfloat16* Bhi2, const __nv_bfloat16* Blo2,
              const float* bias2, float* Cf2,
              int N, int K)
{
    extern __shared__ char smem[];
    const uint32_t sb = smem_u32(smem);
    const uint32_t TILES = (sb + 1023u) & ~1023u;
    const uint32_t STG_SZ = 98304;   // A 2x16KB + B 2x32KB

    bool second = false;
    if (EPI == 3 && blockIdx.z == 1) {
        second = true;
        Ahi = Ahi2; Alo = Alo2; Bhi = Bhi2; Blo = Blo2; bias = bias2; Cf = Cf2;
    }

    const int tid = threadIdx.x, wid = tid >> 5, lane = tid & 31;
    const int bm = blockIdx.y * 128;
    const int bn = blockIdx.x * 256;
    const int warp_m = wid & 1;    // 0..1 -> 64-row slab
    const int warp_n = wid >> 1;   // 0..3 -> 64-col slab
    const int nC = K >> 6;

    auto load_chunk = [&](int ci, int s) {
        const int k0 = ci << 6;
        const uint32_t stg = TILES + s * STG_SZ;
#pragma unroll
        for (int t = 0; t < 4; t++) {                 // A: 128 rows
            const int g = tid + t * 256;
            const int row = g >> 3;
            const int col8 = (g & 7) * 8;             // bf16 elems
            const uint32_t so = swz((uint32_t)(row * 128 + col8 * 2));
            const size_t ia = (size_t)(bm + row) * K + k0 + col8;
            cp16(stg + so,         Ahi + ia);
            cp16(stg + 16384 + so, Alo + ia);
        }
#pragma unroll
        for (int t = 0; t < 8; t++) {                 // B: 256 rows
            const int g = tid + t * 256;
            const int row = g >> 3;
            const int col8 = (g & 7) * 8;
            const uint32_t so = swz((uint32_t)(row * 128 + col8 * 2));
            const size_t ib = (size_t)(bn + row) * K + k0 + col8;
            cp16(stg + 32768 + so, Bhi + ib);
            cp16(stg + 65536 + so, Blo + ib);
        }
        CP_COMMIT();
    };

    // ldmatrix lane address components (round-5 verified formulas)
    const uint32_t mA = warp_m * 64 + ((lane >> 3) & 1) * 8 + (lane & 7);
    const uint32_t kA = (lane >> 4) * 8;
    const uint32_t nB = warp_n * 64 + (lane >> 4) * 8 + (lane & 7);
    const uint32_t kB = ((lane >> 3) & 1) * 8;

    float acc[4][8][4];
#pragma unroll
    for (int i = 0; i < 4; i++)
#pragma unroll
        for (int j = 0; j < 8; j++)
#pragma unroll
            for (int e = 0; e < 4; e++) acc[i][j][e] = 0.f;

    load_chunk(0, 0);
    if (nC > 1) load_chunk(1, 1);

    for (int i = 0; i < nC; i++) {
        const int s = i & 1;
        if (i + 1 < nC) { CP_WAIT(1); } else { CP_WAIT(0); }
        __syncthreads();

        const uint32_t stg = TILES + s * STG_SZ;
        const uint32_t Ahb = stg, Alb = stg + 16384;
        const uint32_t Bhb = stg + 32768, Blb = stg + 65536;

#pragma unroll
        for (int ks = 0; ks < 4; ks++) {
            uint32_t bh[4][4], bl[4][4];
#pragma unroll
            for (int g = 0; g < 4; g++) {
                const uint32_t oB = swz((nB + g * 16) * 128 + (ks * 16 + kB) * 2);
                ldsm4(bh[g], Bhb + oB);
                ldsm4(bl[g], Blb + oB);
            }
#pragma unroll
            for (int mi = 0; mi < 4; mi++) {
                const uint32_t oA = swz((mA + mi * 16) * 128 + (ks * 16 + kA) * 2);
                uint32_t ah[4], al[4];
                ldsm4(ah, Ahb + oA);
                ldsm4(al, Alb + oA);
#pragma unroll
                for (int ni = 0; ni < 8; ni++) {
                    const uint32_t* bhp = &bh[ni >> 1][(ni & 1) * 2];
                    const uint32_t* blp = &bl[ni >> 1][(ni & 1) * 2];
                    mma_bf16(acc[mi][ni], ah, bhp);
                    mma_bf16(acc[mi][ni], ah, blp);
                    mma_bf16(acc[mi][ni], al, bhp);
                }
            }
        }
        __syncthreads();
        if (i + 2 < nC) load_chunk(i + 2, s);
    }

    // ---- Epilogue ----
    const int r0l   = lane >> 2;
    const int cpair = (lane & 3) * 2;
    const int mbase = bm + warp_m * 64;
    const int nbase = bn + warp_n * 64;

#pragma unroll
    for (int mi = 0; mi < 4; mi++) {
        const int row0 = mbase + mi * 16 + r0l;
        const int row1 = row0 + 8;
#pragma unroll
        for (int ni = 0; ni < 8; ni++) {
            const int col = nbase + ni * 8 + cpair;
            const float2 bv = *(const float2*)&bias[col];
            float v0 = acc[mi][ni][0] + bv.x;
            float v1 = acc[mi][ni][1] + bv.y;
            float v2 = acc[mi][ni][2] + bv.x;
            float v3 = acc[mi][ni][3] + bv.y;
            if (EPI == 3 && second) {
                v0 = tanhf(v0); v1 = tanhf(v1); v2 = tanhf(v2); v3 = tanhf(v3);
            }
            if (EPI == 2) {
                __nv_bfloat16 h0, l0, h1, l1;
                split_bf(v0, h0, l0); split_bf(v1, h1, l1);
                *(uint32_t*)&Chi[(size_t)row0 * N + col] = pack2(h0, h1);
                *(uint32_t*)&Clo[(size_t)row0 * N + col] = pack2(l0, l1);
                split_bf(v2, h0, l0); split_bf(v3, h1, l1);
                *(uint32_t*)&Chi[(size_t)row1 * N + col] = pack2(h0, h1);
                *(uint32_t*)&Clo[(size_t)row1 * N + col] = pack2(l0, l1);
            } else {
                *(float2*)&Cf[(size_t)row0 * N + col] = make_float2(v0, v1);
                *(float2*)&Cf[(size_t)row1 * N + col] = make_float2(v2, v3);
            }
        }
    }
}

// ---------------------------------------------------------------------------
// Reductions
// ---------------------------------------------------------------------------
DEVI float2 block_reduce2(float2 v, float2* sbuf) {
    const int lane = threadIdx.x & 31, wid = threadIdx.x >> 5;
#pragma unroll
    for (int o = 16; o > 0; o >>= 1) {
        v.x += __shfl_xor_sync(0xffffffffu, v.x, o);
        v.y += __shfl_xor_sync(0xffffffffu, v.y, o);
    }
    if (lane == 0) sbuf[wid] = v;
    __syncthreads();
    if (wid == 0) {
        float2 t = (lane < 8) ? sbuf[lane] : make_float2(0.f, 0.f);
#pragma unroll
        for (int o = 4; o > 0; o >>= 1) {
            t.x += __shfl_xor_sync(0xffffffffu, t.x, o);
            t.y += __shfl_xor_sync(0xffffffffu, t.y, o);
        }
        if (lane == 0) sbuf[0] = t;
    }
    __syncthreads();
    float2 r = sbuf[0];
    __syncthreads();
    return r;
}

// ---------------------------------------------------------------------------
// Layer-1: 8 rows per block, weights cached in smem (8x less weight traffic)
// smem layout (floats): W float2[4096] | b[4096] | g[4096] | be[4096] = 80KB
// ---------------------------------------------------------------------------
__global__ __launch_bounds__(256)
void layer1_k(const float* __restrict__ x,
              const float* __restrict__ aW1, const float* __restrict__ ab1,
              const float* __restrict__ ag1, const float* __restrict__ abe1,
              const float* __restrict__ pW1, const float* __restrict__ pb1,
              const float* __restrict__ pg1, const float* __restrict__ pbe1,
              __nv_bfloat16* __restrict__ h1h, __nv_bfloat16* __restrict__ h1l,
              __nv_bfloat16* __restrict__ pph, __nv_bfloat16* __restrict__ ppl)
{
    extern __shared__ float sw[];
    float2* W  = (float2*)sw;        // [4096]
    float*  Bb = sw + 8192;          // [4096]
    float*  Gg = sw + 12288;
    float*  Be = sw + 16384;
    __shared__ float2 sbuf[8];

    const int tid = threadIdx.x;
    const int rb = blockIdx.x * 8;

    // ---- amp branch (4096 outputs) ----
    for (int i = tid; i < 4096; i += 256) {
        W[i]  = ((const float2*)aW1)[i];
        Bb[i] = ab1[i]; Gg[i] = ag1[i]; Be[i] = abe1[i];
    }
    __syncthreads();
    for (int r = 0; r < 8; r++) {
        const int b = rb + r;
        const float x0 = x[2 * b], x1 = x[2 * b + 1];
        float2 ss = make_float2(0.f, 0.f);
#pragma unroll
        for (int t = 0; t < 16; t++) {
            const int i = tid + t * 256;
            const float v = fmaf(W[i].y, x1, fmaf(W[i].x, x0, Bb[i]));
            ss.x += v; ss.y += v * v;
        }
        const float2 rr = block_reduce2(ss, sbuf);
        const float m = rr.x * (1.f / 4096.f);
        const float rstd = rsqrtf(rr.y * (1.f / 4096.f) - m * m + 1e-5f);
#pragma unroll
        for (int t = 0; t < 16; t++) {
            const int i = tid + t * 256;
            const float v = fmaf(W[i].y, x1, fmaf(W[i].x, x0, Bb[i]));
            const float hh = (v - m) * rstd * Gg[i] + Be[i];
            const float g = 0.5f * hh * (1.f + erff(hh * 0.70710678118654752f));
            __nv_bfloat16 h, l; split_bf(g, h, l);
            h1h[(size_t)b * 4096 + i] = h;
            h1l[(size_t)b * 4096 + i] = l;
        }
    }
    __syncthreads();

    // ---- phase branch (2048 outputs) ----
    for (int i = tid; i < 2048; i += 256) {
        W[i]  = ((const float2*)pW1)[i];
        Bb[i] = pb1[i]; Gg[i] = pg1[i]; Be[i] = pbe1[i];
    }
    __syncthreads();
    for (int r = 0; r < 8; r++) {
        const int b = rb + r;
        const float x0 = x[2 * b], x1 = x[2 * b + 1];
        float2 ss = make_float2(0.f, 0.f);
#pragma unroll
        for (int t = 0; t < 8; t++) {
            const int i = tid + t * 256;
            const float v = fmaf(W[i].y, x1, fmaf(W[i].x, x0, Bb[i]));
            ss.x += v; ss.y += v * v;
        }
        const float2 rr = block_reduce2(ss, sbuf);
        const float m = rr.x * (1.f / 2048.f);
        const float rstd = rsqrtf(rr.y * (1.f / 2048.f) - m * m + 1e-5f);
#pragma unroll
        for (int t = 0; t < 8; t++) {
            const int i = tid + t * 256;
            const float v = fmaf(W[i].y, x1, fmaf(W[i].x, x0, Bb[i]));
            const float hh = (v - m) * rstd * Gg[i] + Be[i];
            const float s = hh / (1.f + expf(-hh));
            __nv_bfloat16 h, l; split_bf(s, h, l);
            pph[(size_t)b * 2048 + i] = h;
            ppl[(size_t)b * 2048 + i] = l;
        }
    }
}

// ---------------------------------------------------------------------------
// LN + tanh (row 2048) -> bf16 hi/lo
// ---------------------------------------------------------------------------
__global__ __launch_bounds__(256)
void ln_tanh_kernel(const float* __restrict__ in,
                    const float* __restrict__ g, const float* __restrict__ be,
                    __nv_bfloat16* __restrict__ oh, __nv_bfloat16* __restrict__ ol)
{
    __shared__ float2 sbuf[8];
    const int b = blockIdx.x, tid = threadIdx.x;
    const float* row = in + (size_t)b * 2048;
    float va[8];
    float2 ss = make_float2(0.f, 0.f);
#pragma unroll
    for (int t = 0; t < 8; t++) {
        const int i = tid + t * 256;
        const float v = row[i];
        va[t] = v; ss.x += v; ss.y += v * v;
    }
    const float2 r = block_reduce2(ss, sbuf);
    const float m = r.x * (1.f / 2048.f);
    const float rstd = rsqrtf(r.y * (1.f / 2048.f) - m * m + 1e-5f);
#pragma unroll
    for (int t = 0; t < 8; t++) {
        const int i = tid + t * 256;
        const float v = tanhf((va[t] - m) * rstd * g[i] + be[i]);
        __nv_bfloat16 h, l; split_bf(v, h, l);
        oh[(size_t)b * 2048 + i] = h;
        ol[(size_t)b * 2048 + i] = l;
    }
}

// ---------------------------------------------------------------------------
// qs mixing -> bf16 hi/lo
// ---------------------------------------------------------------------------
__global__ __launch_bounds__(256)
void qs_kernel(const float* __restrict__ amp, const float* __restrict__ phv,
               const float* __restrict__ rf, const float* __restrict__ rp,
               __nv_bfloat16* __restrict__ qh, __nv_bfloat16* __restrict__ ql)
{
    const int idx = blockIdx.x * 256 + threadIdx.x;
    const int q = idx & 1023;
    const float* f  = rf + 4 * 1024 * 3 + 3 * q;
    const float* pp = rp + 4 * 1024 * 3 + 3 * q;
    const float rx = sinf(fmaf(amp[idx], f[0], pp[0]));
    const float ry = cosf(fmaf(phv[idx], f[1], pp[1]));
    const float rz = tanhf(pp[2]);
    const float v = (rx + ry + rz) * (1.f / 3.f);
    __nv_bfloat16 h, l; split_bf(v, h, l);
    qh[idx] = h; ql[idx] = l;
}

__global__ __launch_bounds__(256)
void conv_split_kernel(const float* __restrict__ s,
                       __nv_bfloat16* __restrict__ h, __nv_bfloat16* __restrict__ l,
                       int n)
{
    const int i = blockIdx.x * 256 + threadIdx.x;
    if (i < n) {
        __nv_bfloat16 hh, ll; split_bf(s[i], hh, ll);
        h[i] = hh; l[i] = ll;
    }
}

// ---------------------------------------------------------------------------
extern "C" void kernel_launch(void* const* d_in, const int* in_sizes, int n_in,
                              void* d_out, int out_size)
{
    const float* x    = (const float*)d_in[0];
    const float* aW1  = (const float*)d_in[1];
    const float* ab1  = (const float*)d_in[2];
    const float* ag1  = (const float*)d_in[3];
    const float* abe1 = (const float*)d_in[4];
    const float* aW2  = (const float*)d_in[5];
    const float* ab2  = (const float*)d_in[6];
    const float* ag2  = (const float*)d_in[7];
    const float* abe2 = (const float*)d_in[8];
    const float* aW3  = (const float*)d_in[9];
    const float* ab3  = (const float*)d_in[10];
    const float* pW1  = (const float*)d_in[11];
    const float* pb1  = (const float*)d_in[12];
    const float* pg1  = (const float*)d_in[13];
    const float* pbe1 = (const float*)d_in[14];
    const float* pW2  = (const float*)d_in[15];
    const float* pb2  = (const float*)d_in[16];
    const float* rf   = (const float*)d_in[17];
    const float* rp   = (const float*)d_in[18];
    const float* winV = (const float*)d_in[19] + (size_t)2048 * 1024;
    const float* binV = (const float*)d_in[20] + 2048;
    const float* wout = (const float*)d_in[21];
    const float* bout = (const float*)d_in[22];
    float* out = (float*)d_out;

    __nv_bfloat16 *h1h, *h1l, *pph, *ppl, *t2h, *t2l, *qsh, *qsl, *vh, *vl;
    __nv_bfloat16 *w2h, *w2l, *w3h, *w3l, *pw2h, *pw2l, *wvh, *wvl, *woh, *wol;
    float *t2f, *ampf, *phf;
    cudaGetSymbolAddress((void**)&h1h, g_h1h); cudaGetSymbolAddress((void**)&h1l, g_h1l);
    cudaGetSymbolAddress((void**)&pph, g_ph_h); cudaGetSymbolAddress((void**)&ppl, g_ph_l);
    cudaGetSymbolAddress((void**)&t2f, g_t2f);
    cudaGetSymbolAddress((void**)&t2h, g_t2h); cudaGetSymbolAddress((void**)&t2l, g_t2l);
    cudaGetSymbolAddress((void**)&ampf, g_ampf); cudaGetSymbolAddress((void**)&phf, g_phf);
    cudaGetSymbolAddress((void**)&qsh, g_qsh); cudaGetSymbolAddress((void**)&qsl, g_qsl);
    cudaGetSymbolAddress((void**)&vh, g_vh); cudaGetSymbolAddress((void**)&vl, g_vl);
    cudaGetSymbolAddress((void**)&w2h, g_w2h); cudaGetSymbolAddress((void**)&w2l, g_w2l);
    cudaGetSymbolAddress((void**)&w3h, g_w3h); cudaGetSymbolAddress((void**)&w3l, g_w3l);
    cudaGetSymbolAddress((void**)&pw2h, g_pw2h); cudaGetSymbolAddress((void**)&pw2l, g_pw2l);
    cudaGetSymbolAddress((void**)&wvh, g_wvh); cudaGetSymbolAddress((void**)&wvl, g_wvl);
    cudaGetSymbolAddress((void**)&woh, g_woh); cudaGetSymbolAddress((void**)&wol, g_wol);

    const int SMEMB = 1024 + 2 * 98304;   // 197,632 B
    cudaFuncSetAttribute(gemm_bf3<0>, cudaFuncAttributeMaxDynamicSharedMemorySize, SMEMB);
    cudaFuncSetAttribute(gemm_bf3<2>, cudaFuncAttributeMaxDynamicSharedMemorySize, SMEMB);
    cudaFuncSetAttribute(gemm_bf3<3>, cudaFuncAttributeMaxDynamicSharedMemorySize, SMEMB);
    const int L1SMEM = 81920;
    cudaFuncSetAttribute(layer1_k, cudaFuncAttributeMaxDynamicSharedMemorySize, L1SMEM);

    const int M = 16384;

    // idx0: W2 split (needed by gemm1)
    conv_split_kernel<<<(2048 * 4096) / 256, 256>>>(aW2, w2h, w2l, 2048 * 4096);
    // idx1: layer1
    layer1_k<<<M / 8, 256, L1SMEM>>>(x, aW1, ab1, ag1, abe1, pW1, pb1, pg1, pbe1,
                                     h1h, h1l, pph, ppl);
    // idx2: W3 split
    conv_split_kernel<<<(1024 * 2048) / 256, 256>>>(aW3, w3h, w3l, 1024 * 2048);
    // idx3: GEMM1 (profiled by ncu capture window)
    gemm_bf3<0><<<dim3(8, 128), 256, SMEMB>>>(h1h, h1l, w2h, w2l, ab2, t2f,
                                              nullptr, nullptr,
                                              nullptr, nullptr, nullptr, nullptr,
                                              nullptr, nullptr, 2048, 4096);
    // remaining weight splits
    conv_split_kernel<<<(1024 * 2048) / 256, 256>>>(pW2, pw2h, pw2l, 1024 * 2048);
    conv_split_kernel<<<(1024 * 1024) / 256, 256>>>(winV, wvh, wvl, 1024 * 1024);
    conv_split_kernel<<<(1024 * 1024) / 256, 256>>>(wout, woh, wol, 1024 * 1024);

    ln_tanh_kernel<<<M, 256>>>(t2f, ag2, abe2, t2h, t2l);

    // merged GEMM2 (amp) + GEMM3 (phase, tanh): grid z=2
    gemm_bf3<3><<<dim3(4, 128, 2), 256, SMEMB>>>(t2h, t2l, w3h, w3l, ab3, ampf,
                                                 nullptr, nullptr,
                                                 pph, ppl, pw2h, pw2l, pb2, phf,
                                                 1024, 2048);

    qs_kernel<<<(M * 1024) / 256, 256>>>(ampf, phf, rf, rp, qsh, qsl);

    // v = qs @ Wv^T + bv  (bf16 hi/lo epilogue)
    gemm_bf3<2><<<dim3(4, 128), 256, SMEMB>>>(qsh, qsl, wvh, wvl, binV, nullptr,
                                              vh, vl,
                                              nullptr, nullptr, nullptr, nullptr,
                                              nullptr, nullptr, 1024, 1024);

    // out = v @ Wout^T + bout
    gemm_bf3<0><<<dim3(4, 128), 256, SMEMB>>>(vh, vl, woh, wol, bout, out,
                                              nullptr, nullptr,
                                              nullptr, nullptr, nullptr, nullptr,
                                              nullptr, nullptr, 1024, 1024);
}

// round 8
// speedup vs baseline: 3.8864x; 1.3488x over previous
#include <cuda_runtime.h>
#include <cuda_fp16.h>
#include <cstdint>

// ===========================================================================
// B=16384, Q=1024, F=2. Heavy GEMMs: mma.sync m16n8k16 fp16, weights split
// W = Wh + Wl (fp16 planes, ~exact), activations single fp16 plane:
//   C = A*Wh + A*Wl  (2 MMA terms, one fp32 accumulator).
// CTA tile 128x128, K-chunk 64, 4-stage cp.async ring, warp tile 64x32.
// ===========================================================================

#define DEVI __device__ __forceinline__

DEVI uint32_t smem_u32(const void* p) {
    uint32_t r;
    asm("{ .reg .u64 t; cvta.to.shared.u64 t, %1; cvt.u32.u64 %0, t; }"
        : "=r"(r) : "l"(p));
    return r;
}
DEVI uint32_t swz(uint32_t x) { return x ^ ((x >> 3) & 0x70); }

DEVI void cp16(uint32_t dst, const void* src) {
    asm volatile("cp.async.cg.shared.global [%0], [%1], 16;"
                 :: "r"(dst), "l"(src));
}
#define CP_COMMIT() asm volatile("cp.async.commit_group;" ::: "memory")
#define CP_WAIT(n)  asm volatile("cp.async.wait_group %0;" :: "n"(n) : "memory")

DEVI void ldsm4(uint32_t* r, uint32_t a) {
    asm volatile("ldmatrix.sync.aligned.m8n8.x4.shared.b16 {%0,%1,%2,%3}, [%4];"
                 : "=r"(r[0]), "=r"(r[1]), "=r"(r[2]), "=r"(r[3]) : "r"(a));
}
DEVI void mma_f16(float* d, const uint32_t* a, const uint32_t* b) {
    asm volatile("mma.sync.aligned.m16n8k16.row.col.f32.f16.f16.f32 "
                 "{%0,%1,%2,%3},{%4,%5,%6,%7},{%8,%9},{%0,%1,%2,%3};"
                 : "+f"(d[0]), "+f"(d[1]), "+f"(d[2]), "+f"(d[3])
                 : "r"(a[0]), "r"(a[1]), "r"(a[2]), "r"(a[3]),
                   "r"(b[0]), "r"(b[1]));
}

DEVI uint32_t pack2h(__half a, __half b) {
    return (uint32_t)__half_as_ushort(a) | ((uint32_t)__half_as_ushort(b) << 16);
}
DEVI void split_h(float v, __half& h, __half& l) {
    h = __float2half_rn(v);
    l = __float2half_rn(v - __half2float(h));
}

// ---------------------------------------------------------------------------
// Scratch
// ---------------------------------------------------------------------------
__device__ __half g_h1 [(size_t)16384 * 4096];
__device__ __half g_pq [(size_t)16384 * 2048];
__device__ float  g_t2f[(size_t)16384 * 2048];
__device__ __half g_t2q[(size_t)16384 * 2048];
__device__ float  g_ampf[(size_t)16384 * 1024], g_phf[(size_t)16384 * 1024];
__device__ __half g_qs [(size_t)16384 * 1024];
__device__ __half g_v  [(size_t)16384 * 1024];
__device__ __half g_w2h[(size_t)2048 * 4096], g_w2l[(size_t)2048 * 4096];
__device__ __half g_w3h[(size_t)1024 * 2048], g_w3l[(size_t)1024 * 2048];
__device__ __half g_pw2h[(size_t)1024 * 2048], g_pw2l[(size_t)1024 * 2048];
__device__ __half g_wvh[(size_t)1024 * 1024], g_wvl[(size_t)1024 * 1024];
__device__ __half g_woh[(size_t)1024 * 1024], g_wol[(size_t)1024 * 1024];

// ---------------------------------------------------------------------------
// GEMM: C[m,n] = sum_k A[m,k]*(Wh+Wl)[n,k] + bias[n]
// EPI: 0 = fp32 store; 2 = fp16 store (next GEMM's A plane);
//      3 = merged two-GEMM (z==0 -> fp32; z==1 -> set 2 + tanh)
// ---------------------------------------------------------------------------
template<int EPI>
__global__ __launch_bounds__(256, 1)
void gemm_f16w2(const __half* __restrict__ A,
                const __half* __restrict__ Wh, const __half* __restrict__ Wl,
                const float* __restrict__ bias, float* __restrict__ Cf,
                __half* __restrict__ Ch,
                const __half* A2, const __half* Wh2, const __half* Wl2,
                const float* bias2, float* Cf2,
                int N, int K)
{
    extern __shared__ char smem[];
    const uint32_t sb = smem_u32(smem);
    const uint32_t TILES = (sb + 1023u) & ~1023u;
    const uint32_t STG = 49152;          // A 16KB + Wh 16KB + Wl 16KB

    bool second = false;
    if (EPI == 3 && blockIdx.z == 1) {
        second = true;
        A = A2; Wh = Wh2; Wl = Wl2; bias = bias2; Cf = Cf2;
    }

    const int tid = threadIdx.x, wid = tid >> 5, lane = tid & 31;
    const int bm = blockIdx.y * 128, bn = blockIdx.x * 128;
    const int warp_m = wid & 1;     // 64-row slab
    const int warp_n = wid >> 1;    // 32-col slab
    const int nC = K >> 6;

    auto load_chunk = [&](int ci, int s) {
        const int k0 = ci << 6;
        const uint32_t stg = TILES + s * STG;
#pragma unroll
        for (int t = 0; t < 4; t++) {
            const int g = tid + t * 256;
            const int row = g >> 3;
            const int col8 = (g & 7) * 8;
            const uint32_t so = swz((uint32_t)(row * 128 + col8 * 2));
            const size_t ia = (size_t)(bm + row) * K + k0 + col8;
            const size_t ib = (size_t)(bn + row) * K + k0 + col8;
            cp16(stg + so,         A  + ia);
            cp16(stg + 16384 + so, Wh + ib);
            cp16(stg + 32768 + so, Wl + ib);
        }
        CP_COMMIT();
    };

    // ldmatrix lane address components (round-5 verified)
    const uint32_t mA = warp_m * 64 + ((lane >> 3) & 1) * 8 + (lane & 7);
    const uint32_t kA = (lane >> 4) * 8;
    const uint32_t nB = warp_n * 32 + (lane >> 4) * 8 + (lane & 7);
    const uint32_t kB = ((lane >> 3) & 1) * 8;

    float acc[4][4][4];
#pragma unroll
    for (int i = 0; i < 4; i++)
#pragma unroll
        for (int j = 0; j < 4; j++)
#pragma unroll
            for (int e = 0; e < 4; e++) acc[i][j][e] = 0.f;

    load_chunk(0, 0);
    load_chunk(1, 1);
    load_chunk(2, 2);

    for (int i = 0; i < nC; i++) {
        const int s = i & 3;
        if (i < nC - 2)       { CP_WAIT(2); }
        else if (i == nC - 2) { CP_WAIT(1); }
        else                  { CP_WAIT(0); }
        __syncthreads();
        // Stage (i+3)&3 held chunk i-1, consumed in iter i-1; the sync above
        // proves all warps are past it -> safe to refill now (prefetch depth 3).
        if (i + 3 < nC) load_chunk(i + 3, (i + 3) & 3);

        const uint32_t stg = TILES + s * STG;
        const uint32_t Ab = stg, Bhb = stg + 16384, Blb = stg + 32768;

#pragma unroll
        for (int ks = 0; ks < 4; ks++) {
            const uint32_t oB0 = swz(nB * 128 + (ks * 16 + kB) * 2);
            const uint32_t oB1 = swz((nB + 16) * 128 + (ks * 16 + kB) * 2);
            uint32_t bh0[4], bh1[4], bl0[4], bl1[4];
            ldsm4(bh0, Bhb + oB0);
            ldsm4(bh1, Bhb + oB1);
            ldsm4(bl0, Blb + oB0);
            ldsm4(bl1, Blb + oB1);
#pragma unroll
            for (int mi = 0; mi < 4; mi++) {
                const uint32_t oA = swz((mA + mi * 16) * 128 + (ks * 16 + kA) * 2);
                uint32_t ah[4];
                ldsm4(ah, Ab + oA);
#pragma unroll
                for (int ni = 0; ni < 4; ni++) {
                    const uint32_t* bhp = (ni < 2) ? &bh0[(ni & 1) * 2] : &bh1[(ni & 1) * 2];
                    const uint32_t* blp = (ni < 2) ? &bl0[(ni & 1) * 2] : &bl1[(ni & 1) * 2];
                    mma_f16(acc[mi][ni], ah, bhp);
                    mma_f16(acc[mi][ni], ah, blp);
                }
            }
        }
    }

    // ---- Epilogue ----
    const int r0l   = lane >> 2;
    const int cpair = (lane & 3) * 2;
    const int mbase = bm + warp_m * 64;
    const int nbase = bn + warp_n * 32;

#pragma unroll
    for (int mi = 0; mi < 4; mi++) {
        const int row0 = mbase + mi * 16 + r0l;
        const int row1 = row0 + 8;
#pragma unroll
        for (int ni = 0; ni < 4; ni++) {
            const int col = nbase + ni * 8 + cpair;
            const float2 bv = *(const float2*)&bias[col];
            float v0 = acc[mi][ni][0] + bv.x;
            float v1 = acc[mi][ni][1] + bv.y;
            float v2 = acc[mi][ni][2] + bv.x;
            float v3 = acc[mi][ni][3] + bv.y;
            if (EPI == 3 && second) {
                v0 = tanhf(v0); v1 = tanhf(v1); v2 = tanhf(v2); v3 = tanhf(v3);
            }
            if (EPI == 2) {
                *(uint32_t*)&Ch[(size_t)row0 * N + col] =
                    pack2h(__float2half_rn(v0), __float2half_rn(v1));
                *(uint32_t*)&Ch[(size_t)row1 * N + col] =
                    pack2h(__float2half_rn(v2), __float2half_rn(v3));
            } else {
                *(float2*)&Cf[(size_t)row0 * N + col] = make_float2(v0, v1);
                *(float2*)&Cf[(size_t)row1 * N + col] = make_float2(v2, v3);
            }
        }
    }
}

// ---------------------------------------------------------------------------
// Reductions
// ---------------------------------------------------------------------------
DEVI float2 block_reduce2(float2 v, float2* sbuf) {
    const int lane = threadIdx.x & 31, wid = threadIdx.x >> 5;
#pragma unroll
    for (int o = 16; o > 0; o >>= 1) {
        v.x += __shfl_xor_sync(0xffffffffu, v.x, o);
        v.y += __shfl_xor_sync(0xffffffffu, v.y, o);
    }
    if (lane == 0) sbuf[wid] = v;
    __syncthreads();
    if (wid == 0) {
        float2 t = (lane < 8) ? sbuf[lane] : make_float2(0.f, 0.f);
#pragma unroll
        for (int o = 4; o > 0; o >>= 1) {
            t.x += __shfl_xor_sync(0xffffffffu, t.x, o);
            t.y += __shfl_xor_sync(0xffffffffu, t.y, o);
        }
        if (lane == 0) sbuf[0] = t;
    }
    __syncthreads();
    float2 r = sbuf[0];
    __syncthreads();
    return r;
}

// ---------------------------------------------------------------------------
// Layer-1: 8 rows per block, weights cached in smem; outputs fp16 plane
// ---------------------------------------------------------------------------
__global__ __launch_bounds__(256)
void layer1_k(const float* __restrict__ x,
              const float* __restrict__ aW1, const float* __restrict__ ab1,
              const float* __restrict__ ag1, const float* __restrict__ abe1,
              const float* __restrict__ pW1, const float* __restrict__ pb1,
              const float* __restrict__ pg1, const float* __restrict__ pbe1,
              __half* __restrict__ h1, __half* __restrict__ pq)
{
    extern __shared__ float sw[];
    float2* W  = (float2*)sw;
    float*  Bb = sw + 8192;
    float*  Gg = sw + 12288;
    float*  Be = sw + 16384;
    __shared__ float2 sbuf[8];

    const int tid = threadIdx.x;
    const int rb = blockIdx.x * 8;

    for (int i = tid; i < 4096; i += 256) {
        W[i]  = ((const float2*)aW1)[i];
        Bb[i] = ab1[i]; Gg[i] = ag1[i]; Be[i] = abe1[i];
    }
    __syncthreads();
    for (int r = 0; r < 8; r++) {
        const int b = rb + r;
        const float x0 = x[2 * b], x1 = x[2 * b + 1];
        float2 ss = make_float2(0.f, 0.f);
#pragma unroll
        for (int t = 0; t < 16; t++) {
            const int i = tid + t * 256;
            const float v = fmaf(W[i].y, x1, fmaf(W[i].x, x0, Bb[i]));
            ss.x += v; ss.y += v * v;
        }
        const float2 rr = block_reduce2(ss, sbuf);
        const float m = rr.x * (1.f / 4096.f);
        const float rstd = rsqrtf(rr.y * (1.f / 4096.f) - m * m + 1e-5f);
#pragma unroll
        for (int t = 0; t < 16; t++) {
            const int i = tid + t * 256;
            const float v = fmaf(W[i].y, x1, fmaf(W[i].x, x0, Bb[i]));
            const float hh = (v - m) * rstd * Gg[i] + Be[i];
            const float g = 0.5f * hh * (1.f + erff(hh * 0.70710678118654752f));
            h1[(size_t)b * 4096 + i] = __float2half_rn(g);
        }
    }
    __syncthreads();

    for (int i = tid; i < 2048; i += 256) {
        W[i]  = ((const float2*)pW1)[i];
        Bb[i] = pb1[i]; Gg[i] = pg1[i]; Be[i] = pbe1[i];
    }
    __syncthreads();
    for (int r = 0; r < 8; r++) {
        const int b = rb + r;
        const float x0 = x[2 * b], x1 = x[2 * b + 1];
        float2 ss = make_float2(0.f, 0.f);
#pragma unroll
        for (int t = 0; t < 8; t++) {
            const int i = tid + t * 256;
            const float v = fmaf(W[i].y, x1, fmaf(W[i].x, x0, Bb[i]));
            ss.x += v; ss.y += v * v;
        }
        const float2 rr = block_reduce2(ss, sbuf);
        const float m = rr.x * (1.f / 2048.f);
        const float rstd = rsqrtf(rr.y * (1.f / 2048.f) - m * m + 1e-5f);
#pragma unroll
        for (int t = 0; t < 8; t++) {
            const int i = tid + t * 256;
            const float v = fmaf(W[i].y, x1, fmaf(W[i].x, x0, Bb[i]));
            const float hh = (v - m) * rstd * Gg[i] + Be[i];
            const float s = hh / (1.f + expf(-hh));
            pq[(size_t)b * 2048 + i] = __float2half_rn(s);
        }
    }
}

// ---------------------------------------------------------------------------
// LN + tanh (row 2048) -> fp16
// ---------------------------------------------------------------------------
__global__ __launch_bounds__(256)
void ln_tanh_kernel(const float* __restrict__ in,
                    const float* __restrict__ g, const float* __restrict__ be,
                    __half* __restrict__ oq)
{
    __shared__ float2 sbuf[8];
    const int b = blockIdx.x, tid = threadIdx.x;
    const float* row = in + (size_t)b * 2048;
    float va[8];
    float2 ss = make_float2(0.f, 0.f);
#pragma unroll
    for (int t = 0; t < 8; t++) {
        const int i = tid + t * 256;
        const float v = row[i];
        va[t] = v; ss.x += v; ss.y += v * v;
    }
    const float2 r = block_reduce2(ss, sbuf);
    const float m = r.x * (1.f / 2048.f);
    const float rstd = rsqrtf(r.y * (1.f / 2048.f) - m * m + 1e-5f);
#pragma unroll
    for (int t = 0; t < 8; t++) {
        const int i = tid + t * 256;
        const float v = tanhf((va[t] - m) * rstd * g[i] + be[i]);
        oq[(size_t)b * 2048 + i] = __float2half_rn(v);
    }
}

// ---------------------------------------------------------------------------
// qs mixing -> fp16
// ---------------------------------------------------------------------------
__global__ __launch_bounds__(256)
void qs_kernel(const float* __restrict__ amp, const float* __restrict__ phv,
               const float* __restrict__ rf, const float* __restrict__ rp,
               __half* __restrict__ q)
{
    const int idx = blockIdx.x * 256 + threadIdx.x;
    const int qq = idx & 1023;
    const float* f  = rf + 4 * 1024 * 3 + 3 * qq;
    const float* pp = rp + 4 * 1024 * 3 + 3 * qq;
    const float rx = sinf(fmaf(amp[idx], f[0], pp[0]));
    const float ry = cosf(fmaf(phv[idx], f[1], pp[1]));
    const float rz = tanhf(pp[2]);
    q[idx] = __float2half_rn((rx + ry + rz) * (1.f / 3.f));
}

// ---------------------------------------------------------------------------
// Weight split fp32 -> fp16 hi/lo planes
// ---------------------------------------------------------------------------
__global__ __launch_bounds__(256)
void wsplit_kernel(const float* __restrict__ s,
                   __half* __restrict__ h, __half* __restrict__ l, int n)
{
    const int i = blockIdx.x * 256 + threadIdx.x;
    if (i < n) {
        __half hh, ll;
        split_h(s[i], hh, ll);
        h[i] = hh; l[i] = ll;
    }
}

// ---------------------------------------------------------------------------
extern "C" void kernel_launch(void* const* d_in, const int* in_sizes, int n_in,
                              void* d_out, int out_size)
{
    const float* x    = (const float*)d_in[0];
    const float* aW1  = (const float*)d_in[1];
    const float* ab1  = (const float*)d_in[2];
    const float* ag1  = (const float*)d_in[3];
    const float* abe1 = (const float*)d_in[4];
    const float* aW2  = (const float*)d_in[5];
    const float* ab2  = (const float*)d_in[6];
    const float* ag2  = (const float*)d_in[7];
    const float* abe2 = (const float*)d_in[8];
    const float* aW3  = (const float*)d_in[9];
    const float* ab3  = (const float*)d_in[10];
    const float* pW1  = (const float*)d_in[11];
    const float* pb1  = (const float*)d_in[12];
    const float* pg1  = (const float*)d_in[13];
    const float* pbe1 = (const float*)d_in[14];
    const float* pW2  = (const float*)d_in[15];
    const float* pb2  = (const float*)d_in[16];
    const float* rf   = (const float*)d_in[17];
    const float* rp   = (const float*)d_in[18];
    const float* winV = (const float*)d_in[19] + (size_t)2048 * 1024;
    const float* binV = (const float*)d_in[20] + 2048;
    const float* wout = (const float*)d_in[21];
    const float* bout = (const float*)d_in[22];
    float* out = (float*)d_out;

    __half *h1, *pq, *t2q, *qs, *v;
    __half *w2h, *w2l, *w3h, *w3l, *pw2h, *pw2l, *wvh, *wvl, *woh, *wol;
    float *t2f, *ampf, *phf;
    cudaGetSymbolAddress((void**)&h1, g_h1);
    cudaGetSymbolAddress((void**)&pq, g_pq);
    cudaGetSymbolAddress((void**)&t2f, g_t2f);
    cudaGetSymbolAddress((void**)&t2q, g_t2q);
    cudaGetSymbolAddress((void**)&ampf, g_ampf);
    cudaGetSymbolAddress((void**)&phf, g_phf);
    cudaGetSymbolAddress((void**)&qs, g_qs);
    cudaGetSymbolAddress((void**)&v, g_v);
    cudaGetSymbolAddress((void**)&w2h, g_w2h); cudaGetSymbolAddress((void**)&w2l, g_w2l);
    cudaGetSymbolAddress((void**)&w3h, g_w3h); cudaGetSymbolAddress((void**)&w3l, g_w3l);
    cudaGetSymbolAddress((void**)&pw2h, g_pw2h); cudaGetSymbolAddress((void**)&pw2l, g_pw2l);
    cudaGetSymbolAddress((void**)&wvh, g_wvh); cudaGetSymbolAddress((void**)&wvl, g_wvl);
    cudaGetSymbolAddress((void**)&woh, g_woh); cudaGetSymbolAddress((void**)&wol, g_wol);

    const int SMEMB = 1024 + 4 * 49152;   // 197,632 B
    cudaFuncSetAttribute(gemm_f16w2<0>, cudaFuncAttributeMaxDynamicSharedMemorySize, SMEMB);
    cudaFuncSetAttribute(gemm_f16w2<2>, cudaFuncAttributeMaxDynamicSharedMemorySize, SMEMB);
    cudaFuncSetAttribute(gemm_f16w2<3>, cudaFuncAttributeMaxDynamicSharedMemorySize, SMEMB);
    const int L1SMEM = 81920;
    cudaFuncSetAttribute(layer1_k, cudaFuncAttributeMaxDynamicSharedMemorySize, L1SMEM);

    const int M = 16384;

    // idx0: W2 split (needed by gemm1)
    wsplit_kernel<<<(2048 * 4096) / 256, 256>>>(aW2, w2h, w2l, 2048 * 4096);
    // idx1: layer1
    layer1_k<<<M / 8, 256, L1SMEM>>>(x, aW1, ab1, ag1, abe1, pW1, pb1, pg1, pbe1,
                                     h1, pq);
    // idx2: W3 split
    wsplit_kernel<<<(1024 * 2048) / 256, 256>>>(aW3, w3h, w3l, 1024 * 2048);
    // idx3: GEMM1 (16384x2048, K=4096)
    gemm_f16w2<0><<<dim3(16, 128), 256, SMEMB>>>(h1, w2h, w2l, ab2, t2f, nullptr,
                                                 nullptr, nullptr, nullptr,
                                                 nullptr, nullptr, 2048, 4096);
    wsplit_kernel<<<(1024 * 2048) / 256, 256>>>(pW2, pw2h, pw2l, 1024 * 2048);
    wsplit_kernel<<<(1024 * 1024) / 256, 256>>>(winV, wvh, wvl, 1024 * 1024);
    wsplit_kernel<<<(1024 * 1024) / 256, 256>>>(wout, woh, wol, 1024 * 1024);

    ln_tanh_kernel<<<M, 256>>>(t2f, ag2, abe2, t2q);

    // merged GEMM2 (amp, fp32 out) + GEMM3 (phase, tanh epilogue)
    gemm_f16w2<3><<<dim3(8, 128, 2), 256, SMEMB>>>(t2q, w3h, w3l, ab3, ampf, nullptr,
                                                   pq, pw2h, pw2l, pb2, phf,
                                                   1024, 2048);

    qs_kernel<<<(M * 1024) / 256, 256>>>(ampf, phf, rf, rp, qs);

    // v = qs @ Wv^T + bv  (fp16 out -> next GEMM's A)
    gemm_f16w2<2><<<dim3(8, 128), 256, SMEMB>>>(qs, wvh, wvl, binV, nullptr, v,
                                                nullptr, nullptr, nullptr,
                                                nullptr, nullptr, 1024, 1024);

    // out = v @ Wout^T + bout
    gemm_f16w2<0><<<dim3(8, 128), 256, SMEMB>>>(v, woh, wol, bout, out, nullptr,
                                                nullptr, nullptr, nullptr,
                                                nullptr, nullptr, 1024, 1024);
}

// round 10
// speedup vs baseline: 4.2582x; 1.0956x over previous
#include <cuda_runtime.h>
#include <cuda_fp16.h>
#include <cstdint>

// ===========================================================================
// B=16384, Q=1024, F=2. mma.sync m16n8k16 fp16; weights split W = Wh + Wl;
// activations single fp16 plane: C = A*Wh + A*Wl (fp32 accum).
// CTA tile 256(M)x128(N), warp tile 64x64, K-chunk 64.
// 3-stage cp.async ring: preload 2, refill chunk i+2 BEFORE the MMA section
// (stage (i+2)%3 differs from consuming stage i%3 and pending (i+1)%3).
// Last two GEMMs fused: out = qs @ (Wout*Wv)^T + (Wout*bv + bout).
// ===========================================================================

#define DEVI __device__ __forceinline__

DEVI uint32_t smem_u32(const void* p) {
    uint32_t r;
    asm("{ .reg .u64 t; cvta.to.shared.u64 t, %1; cvt.u32.u64 %0, t; }"
        : "=r"(r) : "l"(p));
    return r;
}
DEVI uint32_t swz(uint32_t x) { return x ^ ((x >> 3) & 0x70); }

DEVI void cp16(uint32_t dst, const void* src) {
    asm volatile("cp.async.cg.shared.global [%0], [%1], 16;"
                 :: "r"(dst), "l"(src));
}
#define CP_COMMIT() asm volatile("cp.async.commit_group;" ::: "memory")
#define CP_WAIT(n)  asm volatile("cp.async.wait_group %0;" :: "n"(n) : "memory")

DEVI void ldsm4(uint32_t* r, uint32_t a) {
    asm volatile("ldmatrix.sync.aligned.m8n8.x4.shared.b16 {%0,%1,%2,%3}, [%4];"
                 : "=r"(r[0]), "=r"(r[1]), "=r"(r[2]), "=r"(r[3]) : "r"(a));
}
DEVI void mma_f16(float* d, const uint32_t* a, const uint32_t* b) {
    asm volatile("mma.sync.aligned.m16n8k16.row.col.f32.f16.f16.f32 "
                 "{%0,%1,%2,%3},{%4,%5,%6,%7},{%8,%9},{%0,%1,%2,%3};"
                 : "+f"(d[0]), "+f"(d[1]), "+f"(d[2]), "+f"(d[3])
                 : "r"(a[0]), "r"(a[1]), "r"(a[2]), "r"(a[3]),
                   "r"(b[0]), "r"(b[1]));
}

DEVI void split_h(float v, __half& h, __half& l) {
    h = __float2half_rn(v);
    l = __float2half_rn(v - __half2float(h));
}

// ---------------------------------------------------------------------------
// Scratch
// ---------------------------------------------------------------------------
__device__ __half g_h1 [(size_t)16384 * 4096];
__device__ __half g_pq [(size_t)16384 * 2048];
__device__ float  g_t2f[(size_t)16384 * 2048];
__device__ __half g_t2q[(size_t)16384 * 2048];
__device__ float  g_ampf[(size_t)16384 * 1024], g_phf[(size_t)16384 * 1024];
__device__ __half g_qs [(size_t)16384 * 1024];
__device__ __half g_w2h[(size_t)2048 * 4096], g_w2l[(size_t)2048 * 4096];
__device__ __half g_w3h[(size_t)1024 * 2048], g_w3l[(size_t)1024 * 2048];
__device__ __half g_pw2h[(size_t)1024 * 2048], g_pw2l[(size_t)1024 * 2048];
__device__ __half g_wvth[(size_t)1024 * 1024], g_wvtl[(size_t)1024 * 1024]; // Wv^T planes
__device__ __half g_woh[(size_t)1024 * 1024], g_wol[(size_t)1024 * 1024];   // Wout planes
__device__ float  g_wff[(size_t)1024 * 1024];                               // Wfused fp32
__device__ __half g_wfh[(size_t)1024 * 1024], g_wfl[(size_t)1024 * 1024];   // Wfused planes
__device__ float  g_bfused[1024];
__device__ float  g_bzero[1024];   // zero-initialized (static storage)

// ---------------------------------------------------------------------------
// Main GEMM: C[m,n] = sum_k A[m,k]*(Wh+Wl)[n,k] + bias[n]
// CTA 256x128, 8 warps as 4(m)x2(n), warp tile 64x64.
// EPI: 0 = fp32 store; 3 = merged two-GEMM (z==1 -> second set + tanh)
// ---------------------------------------------------------------------------
template<int EPI>
__global__ __launch_bounds__(256, 1)
void gemm_f16w2(const __half* __restrict__ A,
                const __half* __restrict__ Wh, const __half* __restrict__ Wl,
                const float* __restrict__ bias, float* __restrict__ Cf,
                const __half* A2, const __half* Wh2, const __half* Wl2,
                const float* bias2, float* Cf2,
                int N, int K)
{
    extern __shared__ char smem[];
    const uint32_t sb = smem_u32(smem);
    const uint32_t TILES = (sb + 1023u) & ~1023u;
    const uint32_t STG = 65536;   // A 32KB | Wh 16KB | Wl 16KB

    bool second = false;
    if (EPI == 3 && blockIdx.z == 1) {
        second = true;
        A = A2; Wh = Wh2; Wl = Wl2; bias = bias2; Cf = Cf2;
    }

    const int tid = threadIdx.x, wid = tid >> 5, lane = tid & 31;
    const int bm = blockIdx.y * 256, bn = blockIdx.x * 128;
    const int warp_m = wid & 3;    // 4 x 64-row slab
    const int warp_n = wid >> 2;   // 2 x 64-col slab
    const int nC = K >> 6;

    auto load_chunk = [&](int ci, int s) {
        const int k0 = ci << 6;
        const uint32_t stg = TILES + s * STG;
#pragma unroll
        for (int t = 0; t < 8; t++) {              // A: 256 rows x 64 cols
            const int g = tid + t * 256;
            const int row = g >> 3;
            const int col8 = (g & 7) * 8;
            const uint32_t so = swz((uint32_t)(row * 128 + col8 * 2));
            cp16(stg + so, A + (size_t)(bm + row) * K + k0 + col8);
        }
#pragma unroll
        for (int t = 0; t < 4; t++) {              // W planes: 128 rows
            const int g = tid + t * 256;
            const int row = g >> 3;
            const int col8 = (g & 7) * 8;
            const uint32_t so = swz((uint32_t)(row * 128 + col8 * 2));
            const size_t ib = (size_t)(bn + row) * K + k0 + col8;
            cp16(stg + 32768 + so, Wh + ib);
            cp16(stg + 49152 + so, Wl + ib);
        }
        CP_COMMIT();
    };

    const uint32_t mA = warp_m * 64 + ((lane >> 3) & 1) * 8 + (lane & 7);
    const uint32_t kA = (lane >> 4) * 8;
    const uint32_t nB = warp_n * 64 + (lane >> 4) * 8 + (lane & 7);
    const uint32_t kB = ((lane >> 3) & 1) * 8;

    float acc[4][8][4];
#pragma unroll
    for (int i = 0; i < 4; i++)
#pragma unroll
        for (int j = 0; j < 8; j++)
#pragma unroll
            for (int e = 0; e < 4; e++) acc[i][j][e] = 0.f;

    // 3-stage ring, preload 2 chunks.
    load_chunk(0, 0);
    load_chunk(1, 1);

    for (int i = 0; i < nC; i++) {
        const int s = i - (i / 3) * 3;
        if (i < nC - 1) { CP_WAIT(1); } else { CP_WAIT(0); }
        __syncthreads();
        // Safe refill: stage (i+2)%3 != i%3 (consuming) and != (i+1)%3 (pending).
        if (i + 2 < nC) load_chunk(i + 2, (i + 2) - ((i + 2) / 3) * 3);

        const uint32_t stg = TILES + s * STG;
        const uint32_t Ab = stg, Bhb = stg + 32768, Blb = stg + 49152;

#pragma unroll
        for (int ks = 0; ks < 4; ks++) {
            uint32_t bh[4][4], bl[4][4];
#pragma unroll
            for (int g = 0; g < 4; g++) {
                const uint32_t oB = swz((nB + g * 16) * 128 + (ks * 16 + kB) * 2);
                ldsm4(bh[g], Bhb + oB);
                ldsm4(bl[g], Blb + oB);
            }
#pragma unroll
            for (int mi = 0; mi < 4; mi++) {
                const uint32_t oA = swz((mA + mi * 16) * 128 + (ks * 16 + kA) * 2);
                uint32_t ah[4];
                ldsm4(ah, Ab + oA);
#pragma unroll
                for (int ni = 0; ni < 8; ni++) {
                    const uint32_t* bhp = &bh[ni >> 1][(ni & 1) * 2];
                    const uint32_t* blp = &bl[ni >> 1][(ni & 1) * 2];
                    mma_f16(acc[mi][ni], ah, bhp);
                    mma_f16(acc[mi][ni], ah, blp);
                }
            }
        }
        __syncthreads();   // all warps done reading stage s before next refill targets it
    }

    // ---- Epilogue ----
    const int r0l   = lane >> 2;
    const int cpair = (lane & 3) * 2;
    const int mbase = bm + warp_m * 64;
    const int nbase = bn + warp_n * 64;

#pragma unroll
    for (int mi = 0; mi < 4; mi++) {
        const int row0 = mbase + mi * 16 + r0l;
        const int row1 = row0 + 8;
#pragma unroll
        for (int ni = 0; ni < 8; ni++) {
            const int col = nbase + ni * 8 + cpair;
            const float2 bv = *(const float2*)&bias[col];
            float v0 = acc[mi][ni][0] + bv.x;
            float v1 = acc[mi][ni][1] + bv.y;
            float v2 = acc[mi][ni][2] + bv.x;
            float v3 = acc[mi][ni][3] + bv.y;
            if (EPI == 3 && second) {
                v0 = tanhf(v0); v1 = tanhf(v1); v2 = tanhf(v2); v3 = tanhf(v3);
            }
            *(float2*)&Cf[(size_t)row0 * N + col] = make_float2(v0, v1);
            *(float2*)&Cf[(size_t)row1 * N + col] = make_float2(v2, v3);
        }
    }
}

// ---------------------------------------------------------------------------
// Precompute GEMM (3-term, A 2-plane, fp32-grade): CTA 128x128, warp 64x32.
// C = Ah*Wh + Ah*Wl + Al*Wh + bias. Same safe 3-stage/preload-2 schedule.
// ---------------------------------------------------------------------------
__global__ __launch_bounds__(256, 1)
void gemm3_pre(const __half* __restrict__ Ah, const __half* __restrict__ Al,
               const __half* __restrict__ Wh, const __half* __restrict__ Wl,
               const float* __restrict__ bias, float* __restrict__ Cf,
               int N, int K)
{
    extern __shared__ char smem[];
    const uint32_t sb = smem_u32(smem);
    const uint32_t TILES = (sb + 1023u) & ~1023u;
    const uint32_t STG = 65536;   // Ah|Al|Wh|Wl 16KB each

    const int tid = threadIdx.x, wid = tid >> 5, lane = tid & 31;
    const int bm = blockIdx.y * 128, bn = blockIdx.x * 128;
    const int warp_m = wid & 1, warp_n = wid >> 1;
    const int nC = K >> 6;

    auto load_chunk = [&](int ci, int s) {
        const int k0 = ci << 6;
        const uint32_t stg = TILES + s * STG;
#pragma unroll
        for (int t = 0; t < 4; t++) {
            const int g = tid + t * 256;
            const int row = g >> 3;
            const int col8 = (g & 7) * 8;
            const uint32_t so = swz((uint32_t)(row * 128 + col8 * 2));
            const size_t ia = (size_t)(bm + row) * K + k0 + col8;
            const size_t ib = (size_t)(bn + row) * K + k0 + col8;
            cp16(stg + so,         Ah + ia);
            cp16(stg + 16384 + so, Al + ia);
            cp16(stg + 32768 + so, Wh + ib);
            cp16(stg + 49152 + so, Wl + ib);
        }
        CP_COMMIT();
    };

    const uint32_t mA = warp_m * 64 + ((lane >> 3) & 1) * 8 + (lane & 7);
    const uint32_t kA = (lane >> 4) * 8;
    const uint32_t nB = warp_n * 32 + (lane >> 4) * 8 + (lane & 7);
    const uint32_t kB = ((lane >> 3) & 1) * 8;

    float acc[4][4][4];
#pragma unroll
    for (int i = 0; i < 4; i++)
#pragma unroll
        for (int j = 0; j < 4; j++)
#pragma unroll
            for (int e = 0; e < 4; e++) acc[i][j][e] = 0.f;

    load_chunk(0, 0);
    load_chunk(1, 1);

    for (int i = 0; i < nC; i++) {
        const int s = i - (i / 3) * 3;
        if (i < nC - 1) { CP_WAIT(1); } else { CP_WAIT(0); }
        __syncthreads();
        if (i + 2 < nC) load_chunk(i + 2, (i + 2) - ((i + 2) / 3) * 3);

        const uint32_t stg = TILES + s * STG;
        const uint32_t Ahb = stg, Alb = stg + 16384;
        const uint32_t Bhb = stg + 32768, Blb = stg + 49152;

#pragma unroll
        for (int ks = 0; ks < 4; ks++) {
            const uint32_t oB0 = swz(nB * 128 + (ks * 16 + kB) * 2);
            const uint32_t oB1 = swz((nB + 16) * 128 + (ks * 16 + kB) * 2);
            uint32_t bh0[4], bh1[4], bl0[4], bl1[4];
            ldsm4(bh0, Bhb + oB0);
            ldsm4(bh1, Bhb + oB1);
            ldsm4(bl0, Blb + oB0);
            ldsm4(bl1, Blb + oB1);
#pragma unroll
            for (int mi = 0; mi < 4; mi++) {
                const uint32_t oA = swz((mA + mi * 16) * 128 + (ks * 16 + kA) * 2);
                uint32_t ah[4], al[4];
                ldsm4(ah, Ahb + oA);
                ldsm4(al, Alb + oA);
#pragma unroll
                for (int ni = 0; ni < 4; ni++) {
                    const uint32_t* bhp = (ni < 2) ? &bh0[(ni & 1) * 2] : &bh1[(ni & 1) * 2];
                    const uint32_t* blp = (ni < 2) ? &bl0[(ni & 1) * 2] : &bl1[(ni & 1) * 2];
                    mma_f16(acc[mi][ni], ah, bhp);
                    mma_f16(acc[mi][ni], ah, blp);
                    mma_f16(acc[mi][ni], al, bhp);
                }
            }
        }
        __syncthreads();
    }

    const int r0l   = lane >> 2;
    const int cpair = (lane & 3) * 2;
    const int mbase = bm + warp_m * 64;
    const int nbase = bn + warp_n * 32;
#pragma unroll
    for (int mi = 0; mi < 4; mi++) {
        const int row0 = mbase + mi * 16 + r0l;
        const int row1 = row0 + 8;
#pragma unroll
        for (int ni = 0; ni < 4; ni++) {
            const int col = nbase + ni * 8 + cpair;
            const float2 bv = *(const float2*)&bias[col];
            *(float2*)&Cf[(size_t)row0 * N + col] =
                make_float2(acc[mi][ni][0] + bv.x, acc[mi][ni][1] + bv.y);
            *(float2*)&Cf[(size_t)row1 * N + col] =
                make_float2(acc[mi][ni][2] + bv.x, acc[mi][ni][3] + bv.y);
        }
    }
}

// ---------------------------------------------------------------------------
// Reductions
// ---------------------------------------------------------------------------
DEVI float2 block_reduce2(float2 v, float2* sbuf) {
    const int lane = threadIdx.x & 31, wid = threadIdx.x >> 5;
#pragma unroll
    for (int o = 16; o > 0; o >>= 1) {
        v.x += __shfl_xor_sync(0xffffffffu, v.x, o);
        v.y += __shfl_xor_sync(0xffffffffu, v.y, o);
    }
    if (lane == 0) sbuf[wid] = v;
    __syncthreads();
    if (wid == 0) {
        float2 t = (lane < 8) ? sbuf[lane] : make_float2(0.f, 0.f);
#pragma unroll
        for (int o = 4; o > 0; o >>= 1) {
            t.x += __shfl_xor_sync(0xffffffffu, t.x, o);
            t.y += __shfl_xor_sync(0xffffffffu, t.y, o);
        }
        if (lane == 0) sbuf[0] = t;
    }
    __syncthreads();
    float2 r = sbuf[0];
    __syncthreads();
    return r;
}

// ---------------------------------------------------------------------------
// Layer-1: 8 rows/block, weights cached in smem; fp16 outputs
// ---------------------------------------------------------------------------
__global__ __launch_bounds__(256)
void layer1_k(const float* __restrict__ x,
              const float* __restrict__ aW1, const float* __restrict__ ab1,
              const float* __restrict__ ag1, const float* __restrict__ abe1,
              const float* __restrict__ pW1, const float* __restrict__ pb1,
              const float* __restrict__ pg1, const float* __restrict__ pbe1,
              __half* __restrict__ h1, __half* __restrict__ pq)
{
    extern __shared__ float sw[];
    float2* W  = (float2*)sw;
    float*  Bb = sw + 8192;
    float*  Gg = sw + 12288;
    float*  Be = sw + 16384;
    __shared__ float2 sbuf[8];

    const int tid = threadIdx.x;
    const int rb = blockIdx.x * 8;

    for (int i = tid; i < 4096; i += 256) {
        W[i]  = ((const float2*)aW1)[i];
        Bb[i] = ab1[i]; Gg[i] = ag1[i]; Be[i] = abe1[i];
    }
    __syncthreads();
    for (int r = 0; r < 8; r++) {
        const int b = rb + r;
        const float x0 = x[2 * b], x1 = x[2 * b + 1];
        float2 ss = make_float2(0.f, 0.f);
#pragma unroll
        for (int t = 0; t < 16; t++) {
            const int i = tid + t * 256;
            const float v = fmaf(W[i].y, x1, fmaf(W[i].x, x0, Bb[i]));
            ss.x += v; ss.y += v * v;
        }
        const float2 rr = block_reduce2(ss, sbuf);
        const float m = rr.x * (1.f / 4096.f);
        const float rstd = rsqrtf(rr.y * (1.f / 4096.f) - m * m + 1e-5f);
#pragma unroll
        for (int t = 0; t < 16; t++) {
            const int i = tid + t * 256;
            const float v = fmaf(W[i].y, x1, fmaf(W[i].x, x0, Bb[i]));
            const float hh = (v - m) * rstd * Gg[i] + Be[i];
            const float g = 0.5f * hh * (1.f + erff(hh * 0.70710678118654752f));
            h1[(size_t)b * 4096 + i] = __float2half_rn(g);
        }
    }
    __syncthreads();

    for (int i = tid; i < 2048; i += 256) {
        W[i]  = ((const float2*)pW1)[i];
        Bb[i] = pb1[i]; Gg[i] = pg1[i]; Be[i] = pbe1[i];
    }
    __syncthreads();
    for (int r = 0; r < 8; r++) {
        const int b = rb + r;
        const float x0 = x[2 * b], x1 = x[2 * b + 1];
        float2 ss = make_float2(0.f, 0.f);
#pragma unroll
        for (int t = 0; t < 8; t++) {
            const int i = tid + t * 256;
            const float v = fmaf(W[i].y, x1, fmaf(W[i].x, x0, Bb[i]));
            ss.x += v; ss.y += v * v;
        }
        const float2 rr = block_reduce2(ss, sbuf);
        const float m = rr.x * (1.f / 2048.f);
        const float rstd = rsqrtf(rr.y * (1.f / 2048.f) - m * m + 1e-5f);
#pragma unroll
        for (int t = 0; t < 8; t++) {
            const int i = tid + t * 256;
            const float v = fmaf(W[i].y, x1, fmaf(W[i].x, x0, Bb[i]));
            const float hh = (v - m) * rstd * Gg[i] + Be[i];
            pq[(size_t)b * 2048 + i] = __float2half_rn(hh / (1.f + expf(-hh)));
        }
    }
}

// ---------------------------------------------------------------------------
__global__ __launch_bounds__(256)
void ln_tanh_kernel(const float* __restrict__ in,
                    const float* __restrict__ g, const float* __restrict__ be,
                    __half* __restrict__ oq)
{
    __shared__ float2 sbuf[8];
    const int b = blockIdx.x, tid = threadIdx.x;
    const float* row = in + (size_t)b * 2048;
    float va[8];
    float2 ss = make_float2(0.f, 0.f);
#pragma unroll
    for (int t = 0; t < 8; t++) {
        const int i = tid + t * 256;
        const float v = row[i];
        va[t] = v; ss.x += v; ss.y += v * v;
    }
    const float2 r = block_reduce2(ss, sbuf);
    const float m = r.x * (1.f / 2048.f);
    const float rstd = rsqrtf(r.y * (1.f / 2048.f) - m * m + 1e-5f);
#pragma unroll
    for (int t = 0; t < 8; t++) {
        const int i = tid + t * 256;
        oq[(size_t)b * 2048 + i] =
            __float2half_rn(tanhf((va[t] - m) * rstd * g[i] + be[i]));
    }
}

// ---------------------------------------------------------------------------
__global__ __launch_bounds__(256)
void qs_kernel(const float* __restrict__ amp, const float* __restrict__ phv,
               const float* __restrict__ rf, const float* __restrict__ rp,
               __half* __restrict__ q)
{
    const int idx = blockIdx.x * 256 + threadIdx.x;
    const int qq = idx & 1023;
    const float* f  = rf + 4 * 1024 * 3 + 3 * qq;
    const float* pp = rp + 4 * 1024 * 3 + 3 * qq;
    const float rx = sinf(fmaf(amp[idx], f[0], pp[0]));
    const float ry = cosf(fmaf(phv[idx], f[1], pp[1]));
    const float rz = tanhf(pp[2]);
    q[idx] = __float2half_rn((rx + ry + rz) * (1.f / 3.f));
}

// ---------------------------------------------------------------------------
__global__ __launch_bounds__(256)
void wsplit_kernel(const float* __restrict__ s,
                   __half* __restrict__ h, __half* __restrict__ l, int n)
{
    const int i = blockIdx.x * 256 + threadIdx.x;
    if (i < n) {
        __half hh, ll;
        split_h(s[i], hh, ll);
        h[i] = hh; l[i] = ll;
    }
}

// Transpose-split: th/tl[p*1024+q] = split(W[q*1024+p]); 1024x1024.
__global__ void tsplit_kernel(const float* __restrict__ W,
                              __half* __restrict__ th, __half* __restrict__ tl)
{
    __shared__ float tile[32][33];
    const int tx = threadIdx.x, ty = threadIdx.y;      // (32, 8)
    const int bx = blockIdx.x * 32, by = blockIdx.y * 32;
#pragma unroll
    for (int r = 0; r < 4; r++)
        tile[ty * 4 + r][tx] = W[(size_t)(by + ty * 4 + r) * 1024 + bx + tx];
    __syncthreads();
#pragma unroll
    for (int r = 0; r < 4; r++) {
        const float v = tile[tx][ty * 4 + r];
        __half h, l; split_h(v, h, l);
        const size_t o = (size_t)(bx + ty * 4 + r) * 1024 + by + tx;
        th[o] = h; tl[o] = l;
    }
}

// bfused[o] = dot(Wout[o,:], bv) + bout[o]
__global__ __launch_bounds__(256)
void bfuse_kernel(const float* __restrict__ Wout, const float* __restrict__ bv,
                  const float* __restrict__ bout, float* __restrict__ bf)
{
    __shared__ float2 sbuf[8];
    const int o = blockIdx.x, tid = threadIdx.x;
    float s = 0.f;
#pragma unroll
    for (int t = 0; t < 4; t++) {
        const int i = tid + t * 256;
        s = fmaf(Wout[(size_t)o * 1024 + i], bv[i], s);
    }
    const float2 r = block_reduce2(make_float2(s, 0.f), sbuf);
    if (tid == 0) bf[o] = r.x + bout[o];
}

// ---------------------------------------------------------------------------
extern "C" void kernel_launch(void* const* d_in, const int* in_sizes, int n_in,
                              void* d_out, int out_size)
{
    const float* x    = (const float*)d_in[0];
    const float* aW1  = (const float*)d_in[1];
    const float* ab1  = (const float*)d_in[2];
    const float* ag1  = (const float*)d_in[3];
    const float* abe1 = (const float*)d_in[4];
    const float* aW2  = (const float*)d_in[5];
    const float* ab2  = (const float*)d_in[6];
    const float* ag2  = (const float*)d_in[7];
    const float* abe2 = (const float*)d_in[8];
    const float* aW3  = (const float*)d_in[9];
    const float* ab3  = (const float*)d_in[10];
    const float* pW1  = (const float*)d_in[11];
    const float* pb1  = (const float*)d_in[12];
    const float* pg1  = (const float*)d_in[13];
    const float* pbe1 = (const float*)d_in[14];
    const float* pW2  = (const float*)d_in[15];
    const float* pb2  = (const float*)d_in[16];
    const float* rf   = (const float*)d_in[17];
    const float* rp   = (const float*)d_in[18];
    const float* winV = (const float*)d_in[19] + (size_t)2048 * 1024;
    const float* binV = (const float*)d_in[20] + 2048;
    const float* wout = (const float*)d_in[21];
    const float* bout = (const float*)d_in[22];
    float* out = (float*)d_out;

    __half *h1, *pq, *t2q, *qs;
    __half *w2h, *w2l, *w3h, *w3l, *pw2h, *pw2l, *wvth, *wvtl, *woh, *wol, *wfh, *wfl;
    float *t2f, *ampf, *phf, *wff, *bfused, *bzero;
    cudaGetSymbolAddress((void**)&h1, g_h1);
    cudaGetSymbolAddress((void**)&pq, g_pq);
    cudaGetSymbolAddress((void**)&t2f, g_t2f);
    cudaGetSymbolAddress((void**)&t2q, g_t2q);
    cudaGetSymbolAddress((void**)&ampf, g_ampf);
    cudaGetSymbolAddress((void**)&phf, g_phf);
    cudaGetSymbolAddress((void**)&qs, g_qs);
    cudaGetSymbolAddress((void**)&w2h, g_w2h); cudaGetSymbolAddress((void**)&w2l, g_w2l);
    cudaGetSymbolAddress((void**)&w3h, g_w3h); cudaGetSymbolAddress((void**)&w3l, g_w3l);
    cudaGetSymbolAddress((void**)&pw2h, g_pw2h); cudaGetSymbolAddress((void**)&pw2l, g_pw2l);
    cudaGetSymbolAddress((void**)&wvth, g_wvth); cudaGetSymbolAddress((void**)&wvtl, g_wvtl);
    cudaGetSymbolAddress((void**)&woh, g_woh); cudaGetSymbolAddress((void**)&wol, g_wol);
    cudaGetSymbolAddress((void**)&wff, g_wff);
    cudaGetSymbolAddress((void**)&wfh, g_wfh); cudaGetSymbolAddress((void**)&wfl, g_wfl);
    cudaGetSymbolAddress((void**)&bfused, g_bfused);
    cudaGetSymbolAddress((void**)&bzero, g_bzero);

    const int SMEMB = 1024 + 3 * 65536;   // 197,632 B
    cudaFuncSetAttribute(gemm_f16w2<0>, cudaFuncAttributeMaxDynamicSharedMemorySize, SMEMB);
    cudaFuncSetAttribute(gemm_f16w2<3>, cudaFuncAttributeMaxDynamicSharedMemorySize, SMEMB);
    cudaFuncSetAttribute(gemm3_pre, cudaFuncAttributeMaxDynamicSharedMemorySize, SMEMB);
    const int L1SMEM = 81920;
    cudaFuncSetAttribute(layer1_k, cudaFuncAttributeMaxDynamicSharedMemorySize, L1SMEM);

    const int M = 16384;

    // W2 split (needed first), then layer1
    wsplit_kernel<<<(2048 * 4096) / 256, 256>>>(aW2, w2h, w2l, 2048 * 4096);
    layer1_k<<<M / 8, 256, L1SMEM>>>(x, aW1, ab1, ag1, abe1, pW1, pb1, pg1, pbe1,
                                     h1, pq);
    wsplit_kernel<<<(1024 * 2048) / 256, 256>>>(aW3, w3h, w3l, 1024 * 2048);

    // GEMM1: t2 = h1 @ W2^T + b2  (M x 2048, K=4096)
    gemm_f16w2<0><<<dim3(16, 64), 256, SMEMB>>>(h1, w2h, w2l, ab2, t2f,
                                                nullptr, nullptr, nullptr,
                                                nullptr, nullptr, 2048, 4096);

    // Fused-weight precompute (independent small work)
    wsplit_kernel<<<(1024 * 2048) / 256, 256>>>(pW2, pw2h, pw2l, 1024 * 2048);
    tsplit_kernel<<<dim3(32, 32), dim3(32, 8)>>>(winV, wvth, wvtl);
    wsplit_kernel<<<(1024 * 1024) / 256, 256>>>(wout, woh, wol, 1024 * 1024);
    gemm3_pre<<<dim3(8, 8), 256, SMEMB>>>(woh, wol, wvth, wvtl, bzero, wff,
                                          1024, 1024);
    bfuse_kernel<<<1024, 256>>>(wout, binV, bout, bfused);
    wsplit_kernel<<<(1024 * 1024) / 256, 256>>>(wff, wfh, wfl, 1024 * 1024);

    ln_tanh_kernel<<<M, 256>>>(t2f, ag2, abe2, t2q);

    // merged GEMM2 (amp) + GEMM3 (phase, tanh)
    gemm_f16w2<3><<<dim3(8, 64, 2), 256, SMEMB>>>(t2q, w3h, w3l, ab3, ampf,
                                                  pq, pw2h, pw2l, pb2, phf,
                                                  1024, 2048);

    qs_kernel<<<(M * 1024) / 256, 256>>>(ampf, phf, rf, rp, qs);

    // out = qs @ Wfused^T + bfused   (replaces GEMM4+GEMM5)
    gemm_f16w2<0><<<dim3(8, 64), 256, SMEMB>>>(qs, wfh, wfl, bfused, out,
                                               nullptr, nullptr, nullptr,
                                               nullptr, nullptr, 1024, 1024);
}

// round 11
// speedup vs baseline: 6.8575x; 1.6104x over previous
#include <cuda_runtime.h>
#include <cuda_fp16.h>
#include <cstdint>

// ===========================================================================
// B=16384, Q=1024, F=2. mma.sync m16n8k16 fp16, SINGLE-plane fp16 weights
// and activations (1 MMA term). CTA tile 256(M)x128(N), warp tile 64x64,
// K-chunk 64, 4-stage cp.async ring (round-8 proven schedule).
// Last two GEMMs fused: out = qs @ (Wout*Wv)^T + (Wout*bv + bout);
// Wfused computed on-device in 3-term (fp32-grade) precision.
// ===========================================================================

#define DEVI __device__ __forceinline__

DEVI uint32_t smem_u32(const void* p) {
    uint32_t r;
    asm("{ .reg .u64 t; cvta.to.shared.u64 t, %1; cvt.u32.u64 %0, t; }"
        : "=r"(r) : "l"(p));
    return r;
}
DEVI uint32_t swz(uint32_t x) { return x ^ ((x >> 3) & 0x70); }

DEVI void cp16(uint32_t dst, const void* src) {
    asm volatile("cp.async.cg.shared.global [%0], [%1], 16;"
                 :: "r"(dst), "l"(src));
}
#define CP_COMMIT() asm volatile("cp.async.commit_group;" ::: "memory")
#define CP_WAIT(n)  asm volatile("cp.async.wait_group %0;" :: "n"(n) : "memory")

DEVI void ldsm4(uint32_t* r, uint32_t a) {
    asm volatile("ldmatrix.sync.aligned.m8n8.x4.shared.b16 {%0,%1,%2,%3}, [%4];"
                 : "=r"(r[0]), "=r"(r[1]), "=r"(r[2]), "=r"(r[3]) : "r"(a));
}
DEVI void mma_f16(float* d, const uint32_t* a, const uint32_t* b) {
    asm volatile("mma.sync.aligned.m16n8k16.row.col.f32.f16.f16.f32 "
                 "{%0,%1,%2,%3},{%4,%5,%6,%7},{%8,%9},{%0,%1,%2,%3};"
                 : "+f"(d[0]), "+f"(d[1]), "+f"(d[2]), "+f"(d[3])
                 : "r"(a[0]), "r"(a[1]), "r"(a[2]), "r"(a[3]),
                   "r"(b[0]), "r"(b[1]));
}

DEVI void split_h(float v, __half& h, __half& l) {
    h = __float2half_rn(v);
    l = __float2half_rn(v - __half2float(h));
}

// ---------------------------------------------------------------------------
// Scratch
// ---------------------------------------------------------------------------
__device__ __half g_h1 [(size_t)16384 * 4096];
__device__ __half g_pq [(size_t)16384 * 2048];
__device__ float  g_t2f[(size_t)16384 * 2048];
__device__ __half g_t2q[(size_t)16384 * 2048];
__device__ float  g_ampf[(size_t)16384 * 1024], g_phf[(size_t)16384 * 1024];
__device__ __half g_qs [(size_t)16384 * 1024];
__device__ __half g_w2 [(size_t)2048 * 4096];
__device__ __half g_w3 [(size_t)1024 * 2048];
__device__ __half g_pw2[(size_t)1024 * 2048];
__device__ __half g_wvth[(size_t)1024 * 1024], g_wvtl[(size_t)1024 * 1024]; // Wv^T planes
__device__ __half g_woh[(size_t)1024 * 1024], g_wol[(size_t)1024 * 1024];   // Wout planes
__device__ float  g_wff[(size_t)1024 * 1024];                               // Wfused fp32
__device__ __half g_wf [(size_t)1024 * 1024];                               // Wfused fp16
__device__ float  g_bfused[1024];
__device__ float  g_bzero[1024];   // zero-initialized (static storage)

// ---------------------------------------------------------------------------
// Main GEMM (1-term): C[m,n] = sum_k A[m,k]*W[n,k] + bias[n]
// CTA 256x128, 8 warps as 4(m)x2(n), warp tile 64x64.
// 4-stage ring: preload 3, CP_WAIT(2), sync, refill i+3, MMA. (round-8 proven)
// EPI: 0 = fp32 store; 3 = merged two-GEMM (z==1 -> second set + tanh)
// ---------------------------------------------------------------------------
template<int EPI>
__global__ __launch_bounds__(256, 1)
void gemm_f16(const __half* __restrict__ A, const __half* __restrict__ W,
              const float* __restrict__ bias, float* __restrict__ Cf,
              const __half* A2, const __half* W2p,
              const float* bias2, float* Cf2,
              int N, int K)
{
    extern __shared__ char smem[];
    const uint32_t sb = smem_u32(smem);
    const uint32_t TILES = (sb + 1023u) & ~1023u;
    const uint32_t STG = 49152;   // A 32KB | W 16KB

    bool second = false;
    if (EPI == 3 && blockIdx.z == 1) {
        second = true;
        A = A2; W = W2p; bias = bias2; Cf = Cf2;
    }

    const int tid = threadIdx.x, wid = tid >> 5, lane = tid & 31;
    const int bm = blockIdx.y * 256, bn = blockIdx.x * 128;
    const int warp_m = wid & 3;    // 4 x 64-row slab
    const int warp_n = wid >> 2;   // 2 x 64-col slab
    const int nC = K >> 6;

    auto load_chunk = [&](int ci, int s) {
        const int k0 = ci << 6;
        const uint32_t stg = TILES + s * STG;
#pragma unroll
        for (int t = 0; t < 8; t++) {              // A: 256 rows x 64 cols
            const int g = tid + t * 256;
            const int row = g >> 3;
            const int col8 = (g & 7) * 8;
            const uint32_t so = swz((uint32_t)(row * 128 + col8 * 2));
            cp16(stg + so, A + (size_t)(bm + row) * K + k0 + col8);
        }
#pragma unroll
        for (int t = 0; t < 4; t++) {              // W: 128 rows x 64 cols
            const int g = tid + t * 256;
            const int row = g >> 3;
            const int col8 = (g & 7) * 8;
            const uint32_t so = swz((uint32_t)(row * 128 + col8 * 2));
            cp16(stg + 32768 + so, W + (size_t)(bn + row) * K + k0 + col8);
        }
        CP_COMMIT();
    };

    const uint32_t mA = warp_m * 64 + ((lane >> 3) & 1) * 8 + (lane & 7);
    const uint32_t kA = (lane >> 4) * 8;
    const uint32_t nB = warp_n * 64 + (lane >> 4) * 8 + (lane & 7);
    const uint32_t kB = ((lane >> 3) & 1) * 8;

    float acc[4][8][4];
#pragma unroll
    for (int i = 0; i < 4; i++)
#pragma unroll
        for (int j = 0; j < 8; j++)
#pragma unroll
            for (int e = 0; e < 4; e++) acc[i][j][e] = 0.f;

    // 4-stage ring, preload 3.
    load_chunk(0, 0);
    if (nC > 1) load_chunk(1, 1);
    if (nC > 2) load_chunk(2, 2);

    for (int i = 0; i < nC; i++) {
        const int s = i & 3;
        if (i < nC - 2)       { CP_WAIT(2); }
        else if (i == nC - 2) { CP_WAIT(1); }
        else                  { CP_WAIT(0); }
        __syncthreads();
        // Stage (i+3)&3 was consumed in iter i-1; the barrier above proves all
        // warps are past it -> safe to refill while we MMA stage i&3.
        if (i + 3 < nC) load_chunk(i + 3, (i + 3) & 3);

        const uint32_t stg = TILES + s * STG;
        const uint32_t Ab = stg, Bb = stg + 32768;

#pragma unroll
        for (int ks = 0; ks < 4; ks++) {
            uint32_t bh[4][4];
#pragma unroll
            for (int g = 0; g < 4; g++) {
                const uint32_t oB = swz((nB + g * 16) * 128 + (ks * 16 + kB) * 2);
                ldsm4(bh[g], Bb + oB);
            }
#pragma unroll
            for (int mi = 0; mi < 4; mi++) {
                const uint32_t oA = swz((mA + mi * 16) * 128 + (ks * 16 + kA) * 2);
                uint32_t ah[4];
                ldsm4(ah, Ab + oA);
#pragma unroll
                for (int ni = 0; ni < 8; ni++)
                    mma_f16(acc[mi][ni], ah, &bh[ni >> 1][(ni & 1) * 2]);
            }
        }
    }

    // ---- Epilogue ----
    const int r0l   = lane >> 2;
    const int cpair = (lane & 3) * 2;
    const int mbase = bm + warp_m * 64;
    const int nbase = bn + warp_n * 64;

#pragma unroll
    for (int mi = 0; mi < 4; mi++) {
        const int row0 = mbase + mi * 16 + r0l;
        const int row1 = row0 + 8;
#pragma unroll
        for (int ni = 0; ni < 8; ni++) {
            const int col = nbase + ni * 8 + cpair;
            const float2 bv = *(const float2*)&bias[col];
            float v0 = acc[mi][ni][0] + bv.x;
            float v1 = acc[mi][ni][1] + bv.y;
            float v2 = acc[mi][ni][2] + bv.x;
            float v3 = acc[mi][ni][3] + bv.y;
            if (EPI == 3 && second) {
                v0 = tanhf(v0); v1 = tanhf(v1); v2 = tanhf(v2); v3 = tanhf(v3);
            }
            *(float2*)&Cf[(size_t)row0 * N + col] = make_float2(v0, v1);
            *(float2*)&Cf[(size_t)row1 * N + col] = make_float2(v2, v3);
        }
    }
}

// ---------------------------------------------------------------------------
// Precompute GEMM (3-term, 2-plane both operands): CTA 128x128, warp 64x32.
// C = Ah*Wh + Ah*Wl + Al*Wh + bias.  4-stage ring (same proven schedule).
// ---------------------------------------------------------------------------
__global__ __launch_bounds__(256, 1)
void gemm3_pre(const __half* __restrict__ Ah, const __half* __restrict__ Al,
               const __half* __restrict__ Wh, const __half* __restrict__ Wl,
               const float* __restrict__ bias, float* __restrict__ Cf,
               int N, int K)
{
    extern __shared__ char smem[];
    const uint32_t sb = smem_u32(smem);
    const uint32_t TILES = (sb + 1023u) & ~1023u;
    const uint32_t STG = 65536;   // Ah|Al|Wh|Wl 16KB each (3 stages fit)

    const int tid = threadIdx.x, wid = tid >> 5, lane = tid & 31;
    const int bm = blockIdx.y * 128, bn = blockIdx.x * 128;
    const int warp_m = wid & 1, warp_n = wid >> 1;
    const int nC = K >> 6;

    auto load_chunk = [&](int ci, int s) {
        const int k0 = ci << 6;
        const uint32_t stg = TILES + s * STG;
#pragma unroll
        for (int t = 0; t < 4; t++) {
            const int g = tid + t * 256;
            const int row = g >> 3;
            const int col8 = (g & 7) * 8;
            const uint32_t so = swz((uint32_t)(row * 128 + col8 * 2));
            const size_t ia = (size_t)(bm + row) * K + k0 + col8;
            const size_t ib = (size_t)(bn + row) * K + k0 + col8;
            cp16(stg + so,         Ah + ia);
            cp16(stg + 16384 + so, Al + ia);
            cp16(stg + 32768 + so, Wh + ib);
            cp16(stg + 49152 + so, Wl + ib);
        }
        CP_COMMIT();
    };

    const uint32_t mA = warp_m * 64 + ((lane >> 3) & 1) * 8 + (lane & 7);
    const uint32_t kA = (lane >> 4) * 8;
    const uint32_t nB = warp_n * 32 + (lane >> 4) * 8 + (lane & 7);
    const uint32_t kB = ((lane >> 3) & 1) * 8;

    float acc[4][4][4];
#pragma unroll
    for (int i = 0; i < 4; i++)
#pragma unroll
        for (int j = 0; j < 4; j++)
#pragma unroll
            for (int e = 0; e < 4; e++) acc[i][j][e] = 0.f;

    load_chunk(0, 0);
    if (nC > 1) load_chunk(1, 1);

    for (int i = 0; i < nC; i++) {
        const int s = i - (i / 3) * 3;
        if (i < nC - 1) { CP_WAIT(1); } else { CP_WAIT(0); }
        __syncthreads();
        // 3-stage ring: refill (i+2)%3 differs from consuming i%3 and pending (i+1)%3
        if (i + 2 < nC) load_chunk(i + 2, (i + 2) - ((i + 2) / 3) * 3);

        const uint32_t stg = TILES + s * STG;
        const uint32_t Ahb = stg, Alb = stg + 16384;
        const uint32_t Bhb = stg + 32768, Blb = stg + 49152;

#pragma unroll
        for (int ks = 0; ks < 4; ks++) {
            const uint32_t oB0 = swz(nB * 128 + (ks * 16 + kB) * 2);
            const uint32_t oB1 = swz((nB + 16) * 128 + (ks * 16 + kB) * 2);
            uint32_t bh0[4], bh1[4], bl0[4], bl1[4];
            ldsm4(bh0, Bhb + oB0);
            ldsm4(bh1, Bhb + oB1);
            ldsm4(bl0, Blb + oB0);
            ldsm4(bl1, Blb + oB1);
#pragma unroll
            for (int mi = 0; mi < 4; mi++) {
                const uint32_t oA = swz((mA + mi * 16) * 128 + (ks * 16 + kA) * 2);
                uint32_t ah[4], al[4];
                ldsm4(ah, Ahb + oA);
                ldsm4(al, Alb + oA);
#pragma unroll
                for (int ni = 0; ni < 4; ni++) {
                    const uint32_t* bhp = (ni < 2) ? &bh0[(ni & 1) * 2] : &bh1[(ni & 1) * 2];
                    const uint32_t* blp = (ni < 2) ? &bl0[(ni & 1) * 2] : &bl1[(ni & 1) * 2];
                    mma_f16(acc[mi][ni], ah, bhp);
                    mma_f16(acc[mi][ni], ah, blp);
                    mma_f16(acc[mi][ni], al, bhp);
                }
            }
        }
        __syncthreads();
    }

    const int r0l   = lane >> 2;
    const int cpair = (lane & 3) * 2;
    const int mbase = bm + warp_m * 64;
    const int nbase = bn + warp_n * 32;
#pragma unroll
    for (int mi = 0; mi < 4; mi++) {
        const int row0 = mbase + mi * 16 + r0l;
        const int row1 = row0 + 8;
#pragma unroll
        for (int ni = 0; ni < 4; ni++) {
            const int col = nbase + ni * 8 + cpair;
            const float2 bv = *(const float2*)&bias[col];
            *(float2*)&Cf[(size_t)row0 * N + col] =
                make_float2(acc[mi][ni][0] + bv.x, acc[mi][ni][1] + bv.y);
            *(float2*)&Cf[(size_t)row1 * N + col] =
                make_float2(acc[mi][ni][2] + bv.x, acc[mi][ni][3] + bv.y);
        }
    }
}

// ---------------------------------------------------------------------------
// Reductions
// ---------------------------------------------------------------------------
DEVI float2 block_reduce2(float2 v, float2* sbuf) {
    const int lane = threadIdx.x & 31, wid = threadIdx.x >> 5;
#pragma unroll
    for (int o = 16; o > 0; o >>= 1) {
        v.x += __shfl_xor_sync(0xffffffffu, v.x, o);
        v.y += __shfl_xor_sync(0xffffffffu, v.y, o);
    }
    if (lane == 0) sbuf[wid] = v;
    __syncthreads();
    if (wid == 0) {
        float2 t = (lane < 8) ? sbuf[lane] : make_float2(0.f, 0.f);
#pragma unroll
        for (int o = 4; o > 0; o >>= 1) {
            t.x += __shfl_xor_sync(0xffffffffu, t.x, o);
            t.y += __shfl_xor_sync(0xffffffffu, t.y, o);
        }
        if (lane == 0) sbuf[0] = t;
    }
    __syncthreads();
    float2 r = sbuf[0];
    __syncthreads();
    return r;
}

// ---------------------------------------------------------------------------
// Layer-1: 8 rows/block, weights cached in smem; fp16 outputs
// ---------------------------------------------------------------------------
__global__ __launch_bounds__(256)
void layer1_k(const float* __restrict__ x,
              const float* __restrict__ aW1, const float* __restrict__ ab1,
              const float* __restrict__ ag1, const float* __restrict__ abe1,
              const float* __restrict__ pW1, const float* __restrict__ pb1,
              const float* __restrict__ pg1, const float* __restrict__ pbe1,
              __half* __restrict__ h1, __half* __restrict__ pq)
{
    extern __shared__ float sw[];
    float2* W  = (float2*)sw;
    float*  Bb = sw + 8192;
    float*  Gg = sw + 12288;
    float*  Be = sw + 16384;
    __shared__ float2 sbuf[8];

    const int tid = threadIdx.x;
    const int rb = blockIdx.x * 8;

    for (int i = tid; i < 4096; i += 256) {
        W[i]  = ((const float2*)aW1)[i];
        Bb[i] = ab1[i]; Gg[i] = ag1[i]; Be[i] = abe1[i];
    }
    __syncthreads();
    for (int r = 0; r < 8; r++) {
        const int b = rb + r;
        const float x0 = x[2 * b], x1 = x[2 * b + 1];
        float2 ss = make_float2(0.f, 0.f);
#pragma unroll
        for (int t = 0; t < 16; t++) {
            const int i = tid + t * 256;
            const float v = fmaf(W[i].y, x1, fmaf(W[i].x, x0, Bb[i]));
            ss.x += v; ss.y += v * v;
        }
        const float2 rr = block_reduce2(ss, sbuf);
        const float m = rr.x * (1.f / 4096.f);
        const float rstd = rsqrtf(rr.y * (1.f / 4096.f) - m * m + 1e-5f);
#pragma unroll
        for (int t = 0; t < 16; t++) {
            const int i = tid + t * 256;
            const float v = fmaf(W[i].y, x1, fmaf(W[i].x, x0, Bb[i]));
            const float hh = (v - m) * rstd * Gg[i] + Be[i];
            const float g = 0.5f * hh * (1.f + erff(hh * 0.70710678118654752f));
            h1[(size_t)b * 4096 + i] = __float2half_rn(g);
        }
    }
    __syncthreads();

    for (int i = tid; i < 2048; i += 256) {
        W[i]  = ((const float2*)pW1)[i];
        Bb[i] = pb1[i]; Gg[i] = pg1[i]; Be[i] = pbe1[i];
    }
    __syncthreads();
    for (int r = 0; r < 8; r++) {
        const int b = rb + r;
        const float x0 = x[2 * b], x1 = x[2 * b + 1];
        float2 ss = make_float2(0.f, 0.f);
#pragma unroll
        for (int t = 0; t < 8; t++) {
            const int i = tid + t * 256;
            const float v = fmaf(W[i].y, x1, fmaf(W[i].x, x0, Bb[i]));
            ss.x += v; ss.y += v * v;
        }
        const float2 rr = block_reduce2(ss, sbuf);
        const float m = rr.x * (1.f / 2048.f);
        const float rstd = rsqrtf(rr.y * (1.f / 2048.f) - m * m + 1e-5f);
#pragma unroll
        for (int t = 0; t < 8; t++) {
            const int i = tid + t * 256;
            const float v = fmaf(W[i].y, x1, fmaf(W[i].x, x0, Bb[i]));
            const float hh = (v - m) * rstd * Gg[i] + Be[i];
            pq[(size_t)b * 2048 + i] = __float2half_rn(hh / (1.f + expf(-hh)));
        }
    }
}

// ---------------------------------------------------------------------------
__global__ __launch_bounds__(256)
void ln_tanh_kernel(const float* __restrict__ in,
                    const float* __restrict__ g, const float* __restrict__ be,
                    __half* __restrict__ oq)
{
    __shared__ float2 sbuf[8];
    const int b = blockIdx.x, tid = threadIdx.x;
    const float* row = in + (size_t)b * 2048;
    float va[8];
    float2 ss = make_float2(0.f, 0.f);
#pragma unroll
    for (int t = 0; t < 8; t++) {
        const int i = tid + t * 256;
        const float v = row[i];
        va[t] = v; ss.x += v; ss.y += v * v;
    }
    const float2 r = block_reduce2(ss, sbuf);
    const float m = r.x * (1.f / 2048.f);
    const float rstd = rsqrtf(r.y * (1.f / 2048.f) - m * m + 1e-5f);
#pragma unroll
    for (int t = 0; t < 8; t++) {
        const int i = tid + t * 256;
        oq[(size_t)b * 2048 + i] =
            __float2half_rn(tanhf((va[t] - m) * rstd * g[i] + be[i]));
    }
}

// ---------------------------------------------------------------------------
__global__ __launch_bounds__(256)
void qs_kernel(const float* __restrict__ amp, const float* __restrict__ phv,
               const float* __restrict__ rf, const float* __restrict__ rp,
               __half* __restrict__ q)
{
    const int idx = blockIdx.x * 256 + threadIdx.x;
    const int qq = idx & 1023;
    const float* f  = rf + 4 * 1024 * 3 + 3 * qq;
    const float* pp = rp + 4 * 1024 * 3 + 3 * qq;
    const float rx = sinf(fmaf(amp[idx], f[0], pp[0]));
    const float ry = cosf(fmaf(phv[idx], f[1], pp[1]));
    const float rz = tanhf(pp[2]);
    q[idx] = __float2half_rn((rx + ry + rz) * (1.f / 3.f));
}

// ---------------------------------------------------------------------------
// fp32 -> fp16 (single plane)
__global__ __launch_bounds__(256)
void wconv_kernel(const float* __restrict__ s, __half* __restrict__ h, int n)
{
    const int i = blockIdx.x * 256 + threadIdx.x;
    if (i < n) h[i] = __float2half_rn(s[i]);
}

// fp32 -> fp16 hi/lo planes (used for Wout in the precompute)
__global__ __launch_bounds__(256)
void wsplit_kernel(const float* __restrict__ s,
                   __half* __restrict__ h, __half* __restrict__ l, int n)
{
    const int i = blockIdx.x * 256 + threadIdx.x;
    if (i < n) {
        __half hh, ll;
        split_h(s[i], hh, ll);
        h[i] = hh; l[i] = ll;
    }
}

// Transpose-split: th/tl[p*1024+q] = split(W[q*1024+p]); 1024x1024.
__global__ void tsplit_kernel(const float* __restrict__ W,
                              __half* __restrict__ th, __half* __restrict__ tl)
{
    __shared__ float tile[32][33];
    const int tx = threadIdx.x, ty = threadIdx.y;      // (32, 8)
    const int bx = blockIdx.x * 32, by = blockIdx.y * 32;
#pragma unroll
    for (int r = 0; r < 4; r++)
        tile[ty * 4 + r][tx] = W[(size_t)(by + ty * 4 + r) * 1024 + bx + tx];
    __syncthreads();
#pragma unroll
    for (int r = 0; r < 4; r++) {
        const float v = tile[tx][ty * 4 + r];
        __half h, l; split_h(v, h, l);
        const size_t o = (size_t)(bx + ty * 4 + r) * 1024 + by + tx;
        th[o] = h; tl[o] = l;
    }
}

// bfused[o] = dot(Wout[o,:], bv) + bout[o]
__global__ __launch_bounds__(256)
void bfuse_kernel(const float* __restrict__ Wout, const float* __restrict__ bv,
                  const float* __restrict__ bout, float* __restrict__ bf)
{
    __shared__ float2 sbuf[8];
    const int o = blockIdx.x, tid = threadIdx.x;
    float s = 0.f;
#pragma unroll
    for (int t = 0; t < 4; t++) {
        const int i = tid + t * 256;
        s = fmaf(Wout[(size_t)o * 1024 + i], bv[i], s);
    }
    const float2 r = block_reduce2(make_float2(s, 0.f), sbuf);
    if (tid == 0) bf[o] = r.x + bout[o];
}

// ---------------------------------------------------------------------------
extern "C" void kernel_launch(void* const* d_in, const int* in_sizes, int n_in,
                              void* d_out, int out_size)
{
    const float* x    = (const float*)d_in[0];
    const float* aW1  = (const float*)d_in[1];
    const float* ab1  = (const float*)d_in[2];
    const float* ag1  = (const float*)d_in[3];
    const float* abe1 = (const float*)d_in[4];
    const float* aW2  = (const float*)d_in[5];
    const float* ab2  = (const float*)d_in[6];
    const float* ag2  = (const float*)d_in[7];
    const float* abe2 = (const float*)d_in[8];
    const float* aW3  = (const float*)d_in[9];
    const float* ab3  = (const float*)d_in[10];
    const float* pW1  = (const float*)d_in[11];
    const float* pb1  = (const float*)d_in[12];
    const float* pg1  = (const float*)d_in[13];
    const float* pbe1 = (const float*)d_in[14];
    const float* pW2  = (const float*)d_in[15];
    const float* pb2  = (const float*)d_in[16];
    const float* rf   = (const float*)d_in[17];
    const float* rp   = (const float*)d_in[18];
    const float* winV = (const float*)d_in[19] + (size_t)2048 * 1024;
    const float* binV = (const float*)d_in[20] + 2048;
    const float* wout = (const float*)d_in[21];
    const float* bout = (const float*)d_in[22];
    float* out = (float*)d_out;

    __half *h1, *pq, *t2q, *qs;
    __half *w2, *w3, *pw2, *wvth, *wvtl, *woh, *wol, *wf;
    float *t2f, *ampf, *phf, *wff, *bfused, *bzero;
    cudaGetSymbolAddress((void**)&h1, g_h1);
    cudaGetSymbolAddress((void**)&pq, g_pq);
    cudaGetSymbolAddress((void**)&t2f, g_t2f);
    cudaGetSymbolAddress((void**)&t2q, g_t2q);
    cudaGetSymbolAddress((void**)&ampf, g_ampf);
    cudaGetSymbolAddress((void**)&phf, g_phf);
    cudaGetSymbolAddress((void**)&qs, g_qs);
    cudaGetSymbolAddress((void**)&w2, g_w2);
    cudaGetSymbolAddress((void**)&w3, g_w3);
    cudaGetSymbolAddress((void**)&pw2, g_pw2);
    cudaGetSymbolAddress((void**)&wvth, g_wvth); cudaGetSymbolAddress((void**)&wvtl, g_wvtl);
    cudaGetSymbolAddress((void**)&woh, g_woh); cudaGetSymbolAddress((void**)&wol, g_wol);
    cudaGetSymbolAddress((void**)&wff, g_wff);
    cudaGetSymbolAddress((void**)&wf, g_wf);
    cudaGetSymbolAddress((void**)&bfused, g_bfused);
    cudaGetSymbolAddress((void**)&bzero, g_bzero);

    const int SMEMB = 1024 + 4 * 49152;   // 197,632 B
    cudaFuncSetAttribute(gemm_f16<0>, cudaFuncAttributeMaxDynamicSharedMemorySize, SMEMB);
    cudaFuncSetAttribute(gemm_f16<3>, cudaFuncAttributeMaxDynamicSharedMemorySize, SMEMB);
    const int SMEMP = 1024 + 3 * 65536;
    cudaFuncSetAttribute(gemm3_pre, cudaFuncAttributeMaxDynamicSharedMemorySize, SMEMP);
    const int L1SMEM = 81920;
    cudaFuncSetAttribute(layer1_k, cudaFuncAttributeMaxDynamicSharedMemorySize, L1SMEM);

    const int M = 16384;

    // W2 conversion (needed first), then layer1
    wconv_kernel<<<(2048 * 4096) / 256, 256>>>(aW2, w2, 2048 * 4096);
    layer1_k<<<M / 8, 256, L1SMEM>>>(x, aW1, ab1, ag1, abe1, pW1, pb1, pg1, pbe1,
                                     h1, pq);
    wconv_kernel<<<(1024 * 2048) / 256, 256>>>(aW3, w3, 1024 * 2048);

    // GEMM1: t2 = h1 @ W2^T + b2  (M x 2048, K=4096)
    gemm_f16<0><<<dim3(16, 64), 256, SMEMB>>>(h1, w2, ab2, t2f,
                                              nullptr, nullptr, nullptr, nullptr,
                                              2048, 4096);

    // Fused-weight precompute (independent small work)
    wconv_kernel<<<(1024 * 2048) / 256, 256>>>(pW2, pw2, 1024 * 2048);
    tsplit_kernel<<<dim3(32, 32), dim3(32, 8)>>>(winV, wvth, wvtl);
    wsplit_kernel<<<(1024 * 1024) / 256, 256>>>(wout, woh, wol, 1024 * 1024);
    gemm3_pre<<<dim3(8, 8), 256, SMEMP>>>(woh, wol, wvth, wvtl, bzero, wff,
                                          1024, 1024);
    bfuse_kernel<<<1024, 256>>>(wout, binV, bout, bfused);
    wconv_kernel<<<(1024 * 1024) / 256, 256>>>(wff, wf, 1024 * 1024);

    ln_tanh_kernel<<<M, 256>>>(t2f, ag2, abe2, t2q);

    // merged GEMM2 (amp) + GEMM3 (phase, tanh)
    gemm_f16<3><<<dim3(8, 64, 2), 256, SMEMB>>>(t2q, w3, ab3, ampf,
                                                pq, pw2, pb2, phf,
                                                1024, 2048);

    qs_kernel<<<(M * 1024) / 256, 256>>>(ampf, phf, rf, rp, qs);

    // out = qs @ Wfused^T + bfused   (replaces GEMM4+GEMM5)
    gemm_f16<0><<<dim3(8, 64), 256, SMEMB>>>(qs, wf, bfused, out,
                                             nullptr, nullptr, nullptr, nullptr,
                                             1024, 1024);
}